// round 2
// baseline (speedup 1.0000x reference)
#include <cuda_runtime.h>
#include <cuda_bf16.h>
#include <math.h>

// Problem constants
#define B_  4
#define S_  2048
#define D_  1024
#define H_  16
#define HD_ 64
#define M_  (B_ * S_)          // 8192
#define N_QKV (3 * D_)         // 3072

// ---------------------------------------------------------------------------
// Scratch (device globals: no allocation allowed)
// ---------------------------------------------------------------------------
__device__ float g_qkv[(size_t)M_ * N_QKV];                 // 96 MB
__device__ float g_q[(size_t)B_ * H_ * S_ * HD_];           // 32 MB
__device__ float g_k[(size_t)B_ * H_ * S_ * HD_];           // 32 MB
__device__ float g_v[(size_t)B_ * H_ * S_ * HD_];           // 32 MB
__device__ float g_attn[(size_t)M_ * D_];                   // 32 MB

// ---------------------------------------------------------------------------
// SGEMM: C[M,N] = A[M,K] @ B[N,K]^T   (both row-major, K-major rows)
// 128x128 tile, BK=16, 256 threads, 8x8 microtile.
// M % 128 == 0, N % 128 == 0, K % 16 == 0 (true for all our shapes).
// ---------------------------------------------------------------------------
#define GBM 128
#define GBN 128
#define GBK 16
#define GTM 8
#define GTN 8

__global__ __launch_bounds__(256) void sgemm_abt(
    const float* __restrict__ A, const float* __restrict__ Bm,
    float* __restrict__ C, int M, int N, int K)
{
    __shared__ float As[GBK][GBM];
    __shared__ float Bs[GBK][GBN];

    const int tid = threadIdx.x;
    const int m0 = blockIdx.y * GBM;
    const int n0 = blockIdx.x * GBN;
    const int ty = tid >> 4, tx = tid & 15;
    const int r0 = ty * GTM, c0 = tx * GTN;

    float acc[GTM][GTN];
#pragma unroll
    for (int i = 0; i < GTM; i++)
#pragma unroll
        for (int j = 0; j < GTN; j++) acc[i][j] = 0.f;

    for (int k0 = 0; k0 < K; k0 += GBK) {
#pragma unroll
        for (int l = 0; l < 2; ++l) {
            int lin = l * 256 + tid;        // 0..511 float4 slots
            int row = lin >> 2;             // 0..127
            int c4  = (lin & 3) * 4;        // 0,4,8,12
            float4 a = *(const float4*)&A[(size_t)(m0 + row) * K + k0 + c4];
            As[c4 + 0][row] = a.x; As[c4 + 1][row] = a.y;
            As[c4 + 2][row] = a.z; As[c4 + 3][row] = a.w;
            float4 b = *(const float4*)&Bm[(size_t)(n0 + row) * K + k0 + c4];
            Bs[c4 + 0][row] = b.x; Bs[c4 + 1][row] = b.y;
            Bs[c4 + 2][row] = b.z; Bs[c4 + 3][row] = b.w;
        }
        __syncthreads();

#pragma unroll
        for (int k = 0; k < GBK; ++k) {
            float af[GTM], bf[GTN];
            float4 a0 = *(const float4*)&As[k][r0];
            float4 a1 = *(const float4*)&As[k][r0 + 4];
            af[0]=a0.x; af[1]=a0.y; af[2]=a0.z; af[3]=a0.w;
            af[4]=a1.x; af[5]=a1.y; af[6]=a1.z; af[7]=a1.w;
            float4 b0 = *(const float4*)&Bs[k][c0];
            float4 b1 = *(const float4*)&Bs[k][c0 + 4];
            bf[0]=b0.x; bf[1]=b0.y; bf[2]=b0.z; bf[3]=b0.w;
            bf[4]=b1.x; bf[5]=b1.y; bf[6]=b1.z; bf[7]=b1.w;
#pragma unroll
            for (int i = 0; i < GTM; i++)
#pragma unroll
                for (int j = 0; j < GTN; j++)
                    acc[i][j] += af[i] * bf[j];
        }
        __syncthreads();
    }

#pragma unroll
    for (int i = 0; i < GTM; i++) {
#pragma unroll
        for (int j = 0; j < GTN; j += 4) {
            float4 v = make_float4(acc[i][j], acc[i][j+1], acc[i][j+2], acc[i][j+3]);
            *(float4*)&C[(size_t)(m0 + r0 + i) * N + n0 + c0 + j] = v;
        }
    }
}

// ---------------------------------------------------------------------------
// RoPE + split into per-head layout [B, H, S, HD]
// One thread per (b, s, h, pair i) — handles Q,K (rotated) and V (copy).
// ---------------------------------------------------------------------------
__global__ void rope_split(const float* __restrict__ qkv,
                           float* __restrict__ Q, float* __restrict__ Kh,
                           float* __restrict__ V)
{
    int idx = blockIdx.x * blockDim.x + threadIdx.x;
    const int total = B_ * S_ * H_ * (HD_ / 2);
    if (idx >= total) return;

    int i = idx & 31;            // pair index 0..31
    int t = idx >> 5;
    int h = t & (H_ - 1);
    t >>= 4;
    int s = t & (S_ - 1);
    int b = t >> 11;

    const float* row = qkv + (size_t)(b * S_ + s) * N_QKV;
    int col = h * HD_ + 2 * i;

    float q0 = row[col],            q1 = row[col + 1];
    float k0 = row[D_ + col],       k1 = row[D_ + col + 1];
    float v0 = row[2 * D_ + col],   v1 = row[2 * D_ + col + 1];

    // inv_freq = 10000^(-2i/64); angle = s * inv_freq (fp32, matching reference)
    float inv_freq = (float)pow(10000.0, -(double)(2 * i) / (double)HD_);
    float ang = (float)s * inv_freq;
    float c = cosf(ang), sn = sinf(ang);

    size_t off = (((size_t)b * H_ + h) * S_ + s) * HD_ + 2 * i;
    Q[off]     = q0 * c - q1 * sn;
    Q[off + 1] = q0 * sn + q1 * c;
    Kh[off]     = k0 * c - k1 * sn;
    Kh[off + 1] = k0 * sn + k1 * c;
    V[off]     = v0;
    V[off + 1] = v1;
}

// ---------------------------------------------------------------------------
// Flash attention, fp32. 64 queries x 64 keys per tile, 256 threads,
// 4x4 microtile per thread. Online softmax. Causal + padding mask.
// Ps (probabilities) aliases the Ks buffer -> 48 KB static smem exactly.
// Output written directly in [B, S, D] layout for the O projection.
// ---------------------------------------------------------------------------
#define AB 64

__global__ __launch_bounds__(256) void flash_attn(
    const float* __restrict__ Q, const float* __restrict__ Kg,
    const float* __restrict__ Vg, const int* __restrict__ pad,
    float* __restrict__ O)
{
    __shared__ float Qs[HD_][AB];   // [k][r]  (transposed)
    __shared__ float Ks[HD_][AB];   // [k][c]  (transposed); aliased as Ps[c][r]
    __shared__ float Vs[AB][HD_];   // [c][d]

    const int qi = blockIdx.x, h = blockIdx.y, b = blockIdx.z;
    const int tid = threadIdx.x;
    const int tx = tid & 15, ty = tid >> 4;
    const int q0 = qi * AB;
    const size_t bh = ((size_t)b * H_ + h) * S_;   // row base in [BH][S][HD]
    const float scale = 0.125f;                     // 1/sqrt(64)

    // Load Q tile, transposed into Qs[k][r]
#pragma unroll
    for (int l = 0; l < 4; ++l) {
        int lin = l * 256 + tid;        // 0..1023 float4 slots (64 rows x 16)
        int row = lin >> 4;
        int k4  = (lin & 15) * 4;
        float4 q = *(const float4*)&Q[(bh + q0 + row) * HD_ + k4];
        Qs[k4 + 0][row] = q.x; Qs[k4 + 1][row] = q.y;
        Qs[k4 + 2][row] = q.z; Qs[k4 + 3][row] = q.w;
    }

    float m_i[4], l_i[4], o[4][4];
#pragma unroll
    for (int i = 0; i < 4; i++) {
        m_i[i] = -1e30f; l_i[i] = 0.f;
#pragma unroll
        for (int j = 0; j < 4; j++) o[i][j] = 0.f;
    }

    for (int kv0 = 0; kv0 <= q0; kv0 += AB) {
        __syncthreads();   // prev-iter PV reads done; Qs stores visible (iter 0)

        // Load K (transposed) and V (direct)
#pragma unroll
        for (int l = 0; l < 4; ++l) {
            int lin = l * 256 + tid;
            int row = lin >> 4;
            int k4  = (lin & 15) * 4;
            float4 kv = *(const float4*)&Kg[(bh + kv0 + row) * HD_ + k4];
            Ks[k4 + 0][row] = kv.x; Ks[k4 + 1][row] = kv.y;
            Ks[k4 + 2][row] = kv.z; Ks[k4 + 3][row] = kv.w;
            float4 vv = *(const float4*)&Vg[(bh + kv0 + row) * HD_ + k4];
            *(float4*)&Vs[row][k4] = vv;
        }
        __syncthreads();

        // S = Q K^T  (each thread: rows 4*ty.., cols 4*tx..)
        float s[4][4];
#pragma unroll
        for (int i = 0; i < 4; i++)
#pragma unroll
            for (int j = 0; j < 4; j++) s[i][j] = 0.f;

#pragma unroll
        for (int k = 0; k < HD_; ++k) {
            float4 qv = *(const float4*)&Qs[k][ty * 4];
            float4 kv = *(const float4*)&Ks[k][tx * 4];
            float qa[4] = {qv.x, qv.y, qv.z, qv.w};
            float ka[4] = {kv.x, kv.y, kv.z, kv.w};
#pragma unroll
            for (int i = 0; i < 4; i++)
#pragma unroll
                for (int j = 0; j < 4; j++)
                    s[i][j] += qa[i] * ka[j];
        }
        __syncthreads();   // done reading Ks -> buffer reusable as Ps

        // Scale + causal/padding mask
#pragma unroll
        for (int j = 0; j < 4; j++) {
            int c = kv0 + tx * 4 + j;
            bool pj = (pad[b * S_ + c] != 0);
#pragma unroll
            for (int i = 0; i < 4; i++) {
                int r = q0 + ty * 4 + i;
                bool ok = pj && (c <= r);
                s[i][j] = ok ? s[i][j] * scale : -1e30f;
            }
        }

        // Online softmax. Row owned by the 16 threads sharing ty (same half-warp).
        float* Ps = &Ks[0][0];   // Ps[c][r]
        float p[4][4];
#pragma unroll
        for (int i = 0; i < 4; i++) {
            float mx = fmaxf(fmaxf(s[i][0], s[i][1]), fmaxf(s[i][2], s[i][3]));
#pragma unroll
            for (int off = 1; off < 16; off <<= 1)
                mx = fmaxf(mx, __shfl_xor_sync(0xffffffffu, mx, off));
            float mnew = fmaxf(m_i[i], mx);
            float alpha = __expf(m_i[i] - mnew);
            float rs = 0.f;
#pragma unroll
            for (int j = 0; j < 4; j++) {
                float pj = (s[i][j] <= -1e29f) ? 0.f : __expf(s[i][j] - mnew);
                p[i][j] = pj;
                rs += pj;
            }
#pragma unroll
            for (int off = 1; off < 16; off <<= 1)
                rs += __shfl_xor_sync(0xffffffffu, rs, off);
            l_i[i] = l_i[i] * alpha + rs;
            m_i[i] = mnew;
#pragma unroll
            for (int j = 0; j < 4; j++) o[i][j] *= alpha;
        }

        // Store P transposed: Ps[c][r0..r0+3] as float4 (column j of this thread)
#pragma unroll
        for (int j = 0; j < 4; j++) {
            float4 v = make_float4(p[0][j], p[1][j], p[2][j], p[3][j]);
            *(float4*)&Ps[(tx * 4 + j) * AB + ty * 4] = v;
        }
        __syncthreads();

        // O += P @ V
#pragma unroll
        for (int kk = 0; kk < AB; ++kk) {
            float4 pv = *(const float4*)&Ps[kk * AB + ty * 4];
            float4 vv = *(const float4*)&Vs[kk][tx * 4];
            float pa[4] = {pv.x, pv.y, pv.z, pv.w};
            float va[4] = {vv.x, vv.y, vv.z, vv.w};
#pragma unroll
            for (int i = 0; i < 4; i++)
#pragma unroll
                for (int j = 0; j < 4; j++)
                    o[i][j] += pa[i] * va[j];
        }
    }

    // Normalize and write to [B, S, D] layout (D index = h*64 + d)
#pragma unroll
    for (int i = 0; i < 4; i++) {
        float inv = (l_i[i] > 0.f) ? (1.f / l_i[i]) : 0.f;
        float4 v = make_float4(o[i][0]*inv, o[i][1]*inv, o[i][2]*inv, o[i][3]*inv);
        size_t row = (size_t)b * S_ + q0 + ty * 4 + i;
        *(float4*)&O[row * D_ + h * HD_ + tx * 4] = v;
    }
}

// ---------------------------------------------------------------------------
// Launch
// ---------------------------------------------------------------------------
extern "C" void kernel_launch(void* const* d_in, const int* in_sizes, int n_in,
                              void* d_out, int out_size)
{
    const float* x        = (const float*)d_in[0];
    const int*   pad      = (const int*)d_in[1];
    const float* w_qkv    = (const float*)d_in[2];
    const float* w_o      = (const float*)d_in[3];
    float* out = (float*)d_out;

    float *qkv, *q, *k, *v, *attn;
    cudaGetSymbolAddress((void**)&qkv,  g_qkv);
    cudaGetSymbolAddress((void**)&q,    g_q);
    cudaGetSymbolAddress((void**)&k,    g_k);
    cudaGetSymbolAddress((void**)&v,    g_v);
    cudaGetSymbolAddress((void**)&attn, g_attn);

    // 1) QKV projection: [8192,1024] @ [3072,1024]^T -> [8192,3072]
    {
        dim3 grid(N_QKV / GBN, M_ / GBM);
        sgemm_abt<<<grid, 256>>>(x, w_qkv, qkv, M_, N_QKV, D_);
    }

    // 2) RoPE + head split
    {
        int total = B_ * S_ * H_ * (HD_ / 2);
        rope_split<<<(total + 255) / 256, 256>>>(qkv, q, k, v);
    }

    // 3) Flash attention
    {
        dim3 grid(S_ / AB, H_, B_);
        flash_attn<<<grid, 256>>>(q, k, v, pad, attn);
    }

    // 4) Output projection: [8192,1024] @ [1024,1024]^T -> d_out
    {
        dim3 grid(D_ / GBN, M_ / GBM);
        sgemm_abt<<<grid, 256>>>(attn, w_o, out, M_, D_, D_);
    }
}

// round 6
// speedup vs baseline: 1.4139x; 1.4139x over previous
#include <cuda_runtime.h>
#include <cuda_bf16.h>
#include <math.h>
#include <stdint.h>

// Problem constants
#define B_  4
#define S_  2048
#define D_  1024
#define H_  16
#define HD_ 64
#define M_  (B_ * S_)          // 8192
#define N_QKV (3 * D_)         // 3072
#define K3_ 3072               // 3x split K for bf16x3 GEMMs
#define NIT 96                 // K3_ / 32 mainloop iterations

// ---------------------------------------------------------------------------
// Helpers (sm_80+ baseline features only: mma.sync / ldmatrix / cp.async)
// ---------------------------------------------------------------------------
__device__ __forceinline__ uint32_t smem_u32(const void* p) {
    uint32_t a;
    asm("{ .reg .u64 t; cvta.to.shared.u64 t, %1; cvt.u32.u64 %0, t; }" : "=r"(a) : "l"(p));
    return a;
}
__device__ __forceinline__ void cp_async16(uint32_t s, const void* g) {
    asm volatile("cp.async.cg.shared.global [%0], [%1], 16;" :: "r"(s), "l"(g));
}
#define CP_COMMIT() asm volatile("cp.async.commit_group;")

__device__ __forceinline__ void ldsm4(uint32_t& r0, uint32_t& r1, uint32_t& r2,
                                      uint32_t& r3, uint32_t addr) {
    asm volatile("ldmatrix.sync.aligned.m8n8.x4.shared.b16 {%0,%1,%2,%3}, [%4];"
                 : "=r"(r0), "=r"(r1), "=r"(r2), "=r"(r3) : "r"(addr));
}
__device__ __forceinline__ void mma16816(float* c, const uint32_t* a, const uint32_t* b) {
    asm volatile(
        "mma.sync.aligned.m16n8k16.row.col.f32.bf16.bf16.f32 "
        "{%0,%1,%2,%3}, {%4,%5,%6,%7}, {%8,%9}, {%0,%1,%2,%3};"
        : "+f"(c[0]), "+f"(c[1]), "+f"(c[2]), "+f"(c[3])
        : "r"(a[0]), "r"(a[1]), "r"(a[2]), "r"(a[3]), "r"(b[0]), "r"(b[1]));
}

// Swizzled smem byte offset for tile row (0..127), 16B chunk kc (0..3)
__device__ __forceinline__ uint32_t swz(int row, int kc) {
    return (uint32_t)(row * 64 + ((kc ^ ((row >> 1) & 3)) << 4));
}

// ---------------------------------------------------------------------------
// Scratch (device globals: no allocation allowed)
// ---------------------------------------------------------------------------
__device__ float         g_qkv[(size_t)M_ * N_QKV];          // 96 MB fp32
__device__ float         g_q[(size_t)B_ * H_ * S_ * HD_];    // 32 MB
__device__ float         g_k[(size_t)B_ * H_ * S_ * HD_];    // 32 MB
__device__ float         g_v[(size_t)B_ * H_ * S_ * HD_];    // 32 MB
__device__ __nv_bfloat16 g_x3[(size_t)M_ * K3_];             // 48 MB  [hi|lo|hi]
__device__ __nv_bfloat16 g_wqkv3[(size_t)N_QKV * K3_];       // 18 MB  [hi|hi|lo]
__device__ __nv_bfloat16 g_wo3[(size_t)D_ * K3_];            // 6 MB   [hi|hi|lo]
__device__ __nv_bfloat16 g_attn3[(size_t)M_ * K3_];          // 48 MB  [hi|lo|hi]

// ---------------------------------------------------------------------------
// fp32 -> bf16x3 split. a_type=1: [hi|lo|hi] (A operand); 0: [hi|hi|lo] (B).
// Sum over K3: hi*hi + lo*hi + hi*lo  ==  fp32 product to ~1e-6.
// ---------------------------------------------------------------------------
__global__ void conv_bf16x3(const float* __restrict__ src,
                            __nv_bfloat16* __restrict__ dst,
                            int total, int a_type)
{
    int idx = blockIdx.x * blockDim.x + threadIdx.x;
    if (idx >= total) return;
    int row = idx >> 10;          // K = 1024
    int col = idx & 1023;
    float a = src[idx];
    __nv_bfloat16 hi = __float2bfloat16(a);
    __nv_bfloat16 lo = __float2bfloat16(a - __bfloat162float(hi));
    size_t base = (size_t)row * K3_;
    dst[base + col] = hi;
    dst[base + 1024 + col] = a_type ? lo : hi;
    dst[base + 2048 + col] = a_type ? hi : lo;
}

// ---------------------------------------------------------------------------
// HMMA bf16 GEMM: C[M,N] = A3[M,3072] @ B3[N,3072]^T, fp32 accum.
// 128x128 CTA tile, BK=32, 256 threads (8 warps, 2Mx4N, 64x32 warp tile).
// cp.async double-buffered smem, ldmatrix fragment loads, XOR swizzle.
// ---------------------------------------------------------------------------
__global__ __launch_bounds__(256) void gemm_hmma(
    const __nv_bfloat16* __restrict__ A3,
    const __nv_bfloat16* __restrict__ B3,
    float* __restrict__ C, int N)
{
    __shared__ __align__(128) __nv_bfloat16 As[2][128 * 32];
    __shared__ __align__(128) __nv_bfloat16 Bs[2][128 * 32];

    const int tid = threadIdx.x;
    const int wid = tid >> 5, lane = tid & 31;
    const int m0 = blockIdx.y * 128, n0 = blockIdx.x * 128;
    const int wm = (wid & 1) * 64;        // warp M offset
    const int wn = (wid >> 1) * 32;       // warp N offset

    const uint32_t sA0 = smem_u32(As[0]), sA1 = smem_u32(As[1]);
    const uint32_t sB0 = smem_u32(Bs[0]), sB1 = smem_u32(Bs[1]);

    float acc[4][4][4];
#pragma unroll
    for (int i = 0; i < 4; i++)
#pragma unroll
        for (int j = 0; j < 4; j++)
#pragma unroll
            for (int e = 0; e < 4; e++) acc[i][j][e] = 0.f;

    const int ldrow = tid >> 2;           // 0..63: this thread's load rows
    const int ldkc  = tid & 3;            // 16B chunk within BK=32

    // ---- prologue: load tile 0 into buffer 0
    {
        const int k0 = 0;
#pragma unroll
        for (int l = 0; l < 2; ++l) {
            int row = ldrow + l * 64;
            uint32_t off = swz(row, ldkc);
            cp_async16(sA0 + off, A3 + (size_t)(m0 + row) * K3_ + k0 + ldkc * 8);
            cp_async16(sB0 + off, B3 + (size_t)(n0 + row) * K3_ + k0 + ldkc * 8);
        }
        CP_COMMIT();
    }

    const int lmat = lane >> 3, lr = lane & 7;   // ldmatrix address lane roles

    for (int c = 0; c < NIT; ++c) {
        const int buf = c & 1;
        const uint32_t sa = buf ? sA1 : sA0;
        const uint32_t sb = buf ? sB1 : sB0;

        // prefetch next tile into the other buffer
        if (c + 1 < NIT) {
            const uint32_t na = buf ? sA0 : sA1;
            const uint32_t nb = buf ? sB0 : sB1;
            const int k0 = (c + 1) * 32;
#pragma unroll
            for (int l = 0; l < 2; ++l) {
                int row = ldrow + l * 64;
                uint32_t off = swz(row, ldkc);
                cp_async16(na + off, A3 + (size_t)(m0 + row) * K3_ + k0 + ldkc * 8);
                cp_async16(nb + off, B3 + (size_t)(n0 + row) * K3_ + k0 + ldkc * 8);
            }
            CP_COMMIT();
            asm volatile("cp.async.wait_group 1;");
        } else {
            asm volatile("cp.async.wait_group 0;");
        }
        __syncthreads();

        // ---- compute on buffer `buf` (two k16 steps)
#pragma unroll
        for (int s = 0; s < 2; ++s) {
            uint32_t a[4][4], b[4][2];
#pragma unroll
            for (int i = 0; i < 4; ++i) {
                int row = wm + i * 16 + (lmat & 1) * 8 + lr;
                int kc  = s * 2 + (lmat >> 1);
                ldsm4(a[i][0], a[i][1], a[i][2], a[i][3], sa + swz(row, kc));
            }
#pragma unroll
            for (int j = 0; j < 2; ++j) {
                int row = wn + j * 16 + (lmat >> 1) * 8 + lr;
                int kc  = s * 2 + (lmat & 1);
                uint32_t t0, t1, t2, t3;
                ldsm4(t0, t1, t2, t3, sb + swz(row, kc));
                b[j * 2][0] = t0;     b[j * 2][1] = t1;
                b[j * 2 + 1][0] = t2; b[j * 2 + 1][1] = t3;
            }
#pragma unroll
            for (int i = 0; i < 4; ++i)
#pragma unroll
                for (int j = 0; j < 4; ++j)
                    mma16816(acc[i][j], a[i], b[j]);
        }
        __syncthreads();   // all reads of `buf` done before it is refilled
    }

    // ---- epilogue: fp32 stores (m16n8 frag: rows lane/4, lane/4+8; cols (lane&3)*2)
    const int er = lane >> 2, ec = (lane & 3) * 2;
#pragma unroll
    for (int i = 0; i < 4; ++i) {
#pragma unroll
        for (int j = 0; j < 4; ++j) {
            size_t row = (size_t)(m0 + wm + i * 16 + er);
            int col = n0 + wn + j * 8 + ec;
            *(float2*)&C[row * N + col]       = make_float2(acc[i][j][0], acc[i][j][1]);
            *(float2*)&C[(row + 8) * N + col] = make_float2(acc[i][j][2], acc[i][j][3]);
        }
    }
}

// ---------------------------------------------------------------------------
// RoPE + split into per-head layout [B, H, S, HD]
// ---------------------------------------------------------------------------
__global__ void rope_split(const float* __restrict__ qkv,
                           float* __restrict__ Q, float* __restrict__ Kh,
                           float* __restrict__ V)
{
    int idx = blockIdx.x * blockDim.x + threadIdx.x;
    const int total = B_ * S_ * H_ * (HD_ / 2);
    if (idx >= total) return;

    int i = idx & 31;            // pair index 0..31
    int t = idx >> 5;
    int h = t & (H_ - 1);
    t >>= 4;
    int s = t & (S_ - 1);
    int b = t >> 11;

    const float* row = qkv + (size_t)(b * S_ + s) * N_QKV;
    int col = h * HD_ + 2 * i;

    float q0 = row[col],          q1 = row[col + 1];
    float k0 = row[D_ + col],     k1 = row[D_ + col + 1];
    float v0 = row[2 * D_ + col], v1 = row[2 * D_ + col + 1];

    float inv_freq = (float)pow(10000.0, -(double)(2 * i) / (double)HD_);
    float ang = (float)s * inv_freq;
    float c = cosf(ang), sn = sinf(ang);

    size_t off = (((size_t)b * H_ + h) * S_ + s) * HD_ + 2 * i;
    Q[off]      = q0 * c - q1 * sn;
    Q[off + 1]  = q0 * sn + q1 * c;
    Kh[off]     = k0 * c - k1 * sn;
    Kh[off + 1] = k0 * sn + k1 * c;
    V[off]      = v0;
    V[off + 1]  = v1;
}

// ---------------------------------------------------------------------------
// Flash attention, fp32 (proven core). Epilogue writes the bf16x3 A-operand
// layout [hi|lo|hi] for the HMMA O-projection.
// ---------------------------------------------------------------------------
#define AB 64

__global__ __launch_bounds__(256) void flash_attn(
    const float* __restrict__ Q, const float* __restrict__ Kg,
    const float* __restrict__ Vg, const int* __restrict__ pad,
    __nv_bfloat16* __restrict__ O3)
{
    __shared__ float Qs[HD_][AB];   // [k][r]
    __shared__ float Ks[HD_][AB];   // [k][c]; aliased as Ps[c][r]
    __shared__ float Vs[AB][HD_];   // [c][d]

    const int qi = blockIdx.x, h = blockIdx.y, b = blockIdx.z;
    const int tid = threadIdx.x;
    const int tx = tid & 15, ty = tid >> 4;
    const int q0 = qi * AB;
    const size_t bh = ((size_t)b * H_ + h) * S_;
    const float scale = 0.125f;

#pragma unroll
    for (int l = 0; l < 4; ++l) {
        int lin = l * 256 + tid;
        int row = lin >> 4;
        int k4  = (lin & 15) * 4;
        float4 q = *(const float4*)&Q[(bh + q0 + row) * HD_ + k4];
        Qs[k4 + 0][row] = q.x; Qs[k4 + 1][row] = q.y;
        Qs[k4 + 2][row] = q.z; Qs[k4 + 3][row] = q.w;
    }

    float m_i[4], l_i[4], o[4][4];
#pragma unroll
    for (int i = 0; i < 4; i++) {
        m_i[i] = -1e30f; l_i[i] = 0.f;
#pragma unroll
        for (int j = 0; j < 4; j++) o[i][j] = 0.f;
    }

    for (int kv0 = 0; kv0 <= q0; kv0 += AB) {
        __syncthreads();

#pragma unroll
        for (int l = 0; l < 4; ++l) {
            int lin = l * 256 + tid;
            int row = lin >> 4;
            int k4  = (lin & 15) * 4;
            float4 kv = *(const float4*)&Kg[(bh + kv0 + row) * HD_ + k4];
            Ks[k4 + 0][row] = kv.x; Ks[k4 + 1][row] = kv.y;
            Ks[k4 + 2][row] = kv.z; Ks[k4 + 3][row] = kv.w;
            float4 vv = *(const float4*)&Vg[(bh + kv0 + row) * HD_ + k4];
            *(float4*)&Vs[row][k4] = vv;
        }
        __syncthreads();

        float s[4][4];
#pragma unroll
        for (int i = 0; i < 4; i++)
#pragma unroll
            for (int j = 0; j < 4; j++) s[i][j] = 0.f;

#pragma unroll
        for (int k = 0; k < HD_; ++k) {
            float4 qv = *(const float4*)&Qs[k][ty * 4];
            float4 kv = *(const float4*)&Ks[k][tx * 4];
            float qa[4] = {qv.x, qv.y, qv.z, qv.w};
            float ka[4] = {kv.x, kv.y, kv.z, kv.w};
#pragma unroll
            for (int i = 0; i < 4; i++)
#pragma unroll
                for (int j = 0; j < 4; j++)
                    s[i][j] += qa[i] * ka[j];
        }
        __syncthreads();

#pragma unroll
        for (int j = 0; j < 4; j++) {
            int c = kv0 + tx * 4 + j;
            bool pj = (pad[b * S_ + c] != 0);
#pragma unroll
            for (int i = 0; i < 4; i++) {
                int r = q0 + ty * 4 + i;
                bool ok = pj && (c <= r);
                s[i][j] = ok ? s[i][j] * scale : -1e30f;
            }
        }

        float* Ps = &Ks[0][0];
        float p[4][4];
#pragma unroll
        for (int i = 0; i < 4; i++) {
            float mx = fmaxf(fmaxf(s[i][0], s[i][1]), fmaxf(s[i][2], s[i][3]));
#pragma unroll
            for (int off = 1; off < 16; off <<= 1)
                mx = fmaxf(mx, __shfl_xor_sync(0xffffffffu, mx, off));
            float mnew = fmaxf(m_i[i], mx);
            float alpha = __expf(m_i[i] - mnew);
            float rs = 0.f;
#pragma unroll
            for (int j = 0; j < 4; j++) {
                float pj = (s[i][j] <= -1e29f) ? 0.f : __expf(s[i][j] - mnew);
                p[i][j] = pj;
                rs += pj;
            }
#pragma unroll
            for (int off = 1; off < 16; off <<= 1)
                rs += __shfl_xor_sync(0xffffffffu, rs, off);
            l_i[i] = l_i[i] * alpha + rs;
            m_i[i] = mnew;
#pragma unroll
            for (int j = 0; j < 4; j++) o[i][j] *= alpha;
        }

#pragma unroll
        for (int j = 0; j < 4; j++) {
            float4 v = make_float4(p[0][j], p[1][j], p[2][j], p[3][j]);
            *(float4*)&Ps[(tx * 4 + j) * AB + ty * 4] = v;
        }
        __syncthreads();

#pragma unroll
        for (int kk = 0; kk < AB; ++kk) {
            float4 pv = *(const float4*)&Ps[kk * AB + ty * 4];
            float4 vv = *(const float4*)&Vs[kk][tx * 4];
            float pa[4] = {pv.x, pv.y, pv.z, pv.w};
            float va[4] = {vv.x, vv.y, vv.z, vv.w};
#pragma unroll
            for (int i = 0; i < 4; i++)
#pragma unroll
                for (int j = 0; j < 4; j++)
                    o[i][j] += pa[i] * va[j];
        }
    }

    // normalize + write bf16x3 [hi|lo|hi] rows of width 3072
#pragma unroll
    for (int i = 0; i < 4; i++) {
        float inv = (l_i[i] > 0.f) ? (1.f / l_i[i]) : 0.f;
        float val[4];
        __nv_bfloat16 hi[4], lo[4];
#pragma unroll
        for (int j = 0; j < 4; j++) {
            val[j] = o[i][j] * inv;
            hi[j] = __float2bfloat16(val[j]);
            lo[j] = __float2bfloat16(val[j] - __bfloat162float(hi[j]));
        }
        size_t row = (size_t)b * S_ + q0 + ty * 4 + i;
        size_t base = row * K3_ + h * HD_ + tx * 4;
        __nv_bfloat162* d0 = (__nv_bfloat162*)(O3 + base);
        __nv_bfloat162* d1 = (__nv_bfloat162*)(O3 + base + 1024);
        __nv_bfloat162* d2 = (__nv_bfloat162*)(O3 + base + 2048);
        d0[0] = __halves2bfloat162(hi[0], hi[1]); d0[1] = __halves2bfloat162(hi[2], hi[3]);
        d1[0] = __halves2bfloat162(lo[0], lo[1]); d1[1] = __halves2bfloat162(lo[2], lo[3]);
        d2[0] = __halves2bfloat162(hi[0], hi[1]); d2[1] = __halves2bfloat162(hi[2], hi[3]);
    }
}

// ---------------------------------------------------------------------------
// Launch
// ---------------------------------------------------------------------------
extern "C" void kernel_launch(void* const* d_in, const int* in_sizes, int n_in,
                              void* d_out, int out_size)
{
    const float* x     = (const float*)d_in[0];
    const int*   pad   = (const int*)d_in[1];
    const float* w_qkv = (const float*)d_in[2];
    const float* w_o   = (const float*)d_in[3];
    float* out = (float*)d_out;

    float *qkv, *q, *k, *v;
    __nv_bfloat16 *x3, *wqkv3, *wo3, *attn3;
    cudaGetSymbolAddress((void**)&qkv,   g_qkv);
    cudaGetSymbolAddress((void**)&q,     g_q);
    cudaGetSymbolAddress((void**)&k,     g_k);
    cudaGetSymbolAddress((void**)&v,     g_v);
    cudaGetSymbolAddress((void**)&x3,    g_x3);
    cudaGetSymbolAddress((void**)&wqkv3, g_wqkv3);
    cudaGetSymbolAddress((void**)&wo3,   g_wo3);
    cudaGetSymbolAddress((void**)&attn3, g_attn3);

    // 0) fp32 -> bf16x3 splits
    {
        int txc = M_ * D_;
        conv_bf16x3<<<(txc + 255) / 256, 256>>>(x, x3, txc, 1);
        int tw = N_QKV * D_;
        conv_bf16x3<<<(tw + 255) / 256, 256>>>(w_qkv, wqkv3, tw, 0);
        int to = D_ * D_;
        conv_bf16x3<<<(to + 255) / 256, 256>>>(w_o, wo3, to, 0);
    }

    // 1) QKV projection (HMMA): [8192,3072] @ [3072,3072]^T -> fp32
    {
        dim3 grid(N_QKV / 128, M_ / 128);
        gemm_hmma<<<grid, 256>>>(x3, wqkv3, qkv, N_QKV);
    }

    // 2) RoPE + head split
    {
        int total = B_ * S_ * H_ * (HD_ / 2);
        rope_split<<<(total + 255) / 256, 256>>>(qkv, q, k, v);
    }

    // 3) Flash attention (fp32 core, bf16x3 epilogue)
    {
        dim3 grid(S_ / AB, H_, B_);
        flash_attn<<<grid, 256>>>(q, k, v, pad, attn3);
    }

    // 4) Output projection (HMMA) -> d_out (fp32)
    {
        dim3 grid(D_ / 128, M_ / 128);
        gemm_hmma<<<grid, 256>>>(attn3, wo3, out, D_);
    }
}

// round 7
// speedup vs baseline: 2.2029x; 1.5580x over previous
#include <cuda_runtime.h>
#include <cuda_bf16.h>
#include <math.h>
#include <stdint.h>

// Problem constants
#define B_  4
#define S_  2048
#define D_  1024
#define H_  16
#define HD_ 64
#define M_  (B_ * S_)          // 8192
#define N_QKV (3 * D_)         // 3072
#define K3_ 3072               // 3x split K for bf16x3 GEMMs
#define NIT 96                 // K3_ / 32 mainloop iterations

// ---------------------------------------------------------------------------
// Helpers (sm_80+ baseline features only: mma.sync / ldmatrix / cp.async)
// ---------------------------------------------------------------------------
__device__ __forceinline__ uint32_t smem_u32(const void* p) {
    uint32_t a;
    asm("{ .reg .u64 t; cvta.to.shared.u64 t, %1; cvt.u32.u64 %0, t; }" : "=r"(a) : "l"(p));
    return a;
}
__device__ __forceinline__ void cp_async16(uint32_t s, const void* g) {
    asm volatile("cp.async.cg.shared.global [%0], [%1], 16;" :: "r"(s), "l"(g));
}
#define CP_COMMIT() asm volatile("cp.async.commit_group;")

__device__ __forceinline__ void ldsm4(uint32_t& r0, uint32_t& r1, uint32_t& r2,
                                      uint32_t& r3, uint32_t addr) {
    asm volatile("ldmatrix.sync.aligned.m8n8.x4.shared.b16 {%0,%1,%2,%3}, [%4];"
                 : "=r"(r0), "=r"(r1), "=r"(r2), "=r"(r3) : "r"(addr));
}
__device__ __forceinline__ void mma16816(float* c, const uint32_t* a, const uint32_t* b) {
    asm volatile(
        "mma.sync.aligned.m16n8k16.row.col.f32.bf16.bf16.f32 "
        "{%0,%1,%2,%3}, {%4,%5,%6,%7}, {%8,%9}, {%0,%1,%2,%3};"
        : "+f"(c[0]), "+f"(c[1]), "+f"(c[2]), "+f"(c[3])
        : "r"(a[0]), "r"(a[1]), "r"(a[2]), "r"(a[3]), "r"(b[0]), "r"(b[1]));
}

// fast exp2 on FMA pipe (arg in [-126, 0]); ~1e-6 relative error
__device__ __forceinline__ float exp2p(float x) {
    x = fmaxf(x, -126.f);
    int n = __float2int_rn(x);
    float f = x - (float)n;
    float p = fmaf(0.00133335581f, f, 0.00961812911f);
    p = fmaf(p, f, 0.0555041087f);
    p = fmaf(p, f, 0.240226507f);
    p = fmaf(p, f, 0.693147181f);
    p = fmaf(p, f, 1.0f);
    return __int_as_float((n + 127) << 23) * p;
}

__device__ __forceinline__ uint32_t pack_bf2(float a, float b) {
    __nv_bfloat162 t = __floats2bfloat162_rn(a, b);   // .x = a (low)
    return *reinterpret_cast<uint32_t*>(&t);
}

// Swizzled byte offset, 256B rows, 16B chunk index c (0..15); xor low 3 bits
__device__ __forceinline__ uint32_t swz16(int row, int c) {
    return (uint32_t)(row * 256 + ((c ^ (row & 7)) << 4));
}
// 128B-row swizzle for the GEMM (as round 6)
__device__ __forceinline__ uint32_t swz(int row, int kc) {
    return (uint32_t)(row * 64 + ((kc ^ ((row >> 1) & 3)) << 4));
}

// ---------------------------------------------------------------------------
// Scratch (device globals: no allocation allowed)
// ---------------------------------------------------------------------------
__device__ float         g_qkv[(size_t)M_ * N_QKV];          // 96 MB fp32
__device__ __nv_bfloat16 g_x3[(size_t)M_ * K3_];             // [hi|lo|hi]
__device__ __nv_bfloat16 g_wqkv3[(size_t)N_QKV * K3_];       // [hi|hi|lo]
__device__ __nv_bfloat16 g_wo3[(size_t)D_ * K3_];            // [hi|hi|lo]
__device__ __nv_bfloat16 g_attn3[(size_t)M_ * K3_];          // [hi|lo|hi]
// attention operands, bf16 hi/lo panels
#define BHSD ((size_t)B_ * H_ * S_ * HD_)
__device__ __nv_bfloat16 g_qhi[BHSD], g_qlo[BHSD];           // [bh][s][64]
__device__ __nv_bfloat16 g_khi[BHSD], g_klo[BHSD];           // [bh][s][64]
__device__ __nv_bfloat16 g_vthi[BHSD], g_vtlo[BHSD];         // [bh][64][S] (transposed)

// ---------------------------------------------------------------------------
// fp32 -> bf16x3 split. a_type=1: [hi|lo|hi] (A operand); 0: [hi|hi|lo] (B).
// ---------------------------------------------------------------------------
__global__ void conv_bf16x3(const float* __restrict__ src,
                            __nv_bfloat16* __restrict__ dst,
                            int total, int a_type)
{
    int idx = blockIdx.x * blockDim.x + threadIdx.x;
    if (idx >= total) return;
    int row = idx >> 10;          // K = 1024
    int col = idx & 1023;
    float a = src[idx];
    __nv_bfloat16 hi = __float2bfloat16(a);
    __nv_bfloat16 lo = __float2bfloat16(a - __bfloat162float(hi));
    size_t base = (size_t)row * K3_;
    dst[base + col] = hi;
    dst[base + 1024 + col] = a_type ? lo : hi;
    dst[base + 2048 + col] = a_type ? hi : lo;
}

// ---------------------------------------------------------------------------
// HMMA bf16 GEMM (unchanged from round 6; verified)
// ---------------------------------------------------------------------------
__global__ __launch_bounds__(256) void gemm_hmma(
    const __nv_bfloat16* __restrict__ A3,
    const __nv_bfloat16* __restrict__ B3,
    float* __restrict__ C, int N)
{
    __shared__ __align__(128) __nv_bfloat16 As[2][128 * 32];
    __shared__ __align__(128) __nv_bfloat16 Bs[2][128 * 32];

    const int tid = threadIdx.x;
    const int wid = tid >> 5, lane = tid & 31;
    const int m0 = blockIdx.y * 128, n0 = blockIdx.x * 128;
    const int wm = (wid & 1) * 64;
    const int wn = (wid >> 1) * 32;

    const uint32_t sA0 = smem_u32(As[0]), sA1 = smem_u32(As[1]);
    const uint32_t sB0 = smem_u32(Bs[0]), sB1 = smem_u32(Bs[1]);

    float acc[4][4][4];
#pragma unroll
    for (int i = 0; i < 4; i++)
#pragma unroll
        for (int j = 0; j < 4; j++)
#pragma unroll
            for (int e = 0; e < 4; e++) acc[i][j][e] = 0.f;

    const int ldrow = tid >> 2;
    const int ldkc  = tid & 3;

    {
#pragma unroll
        for (int l = 0; l < 2; ++l) {
            int row = ldrow + l * 64;
            uint32_t off = swz(row, ldkc);
            cp_async16(sA0 + off, A3 + (size_t)(m0 + row) * K3_ + ldkc * 8);
            cp_async16(sB0 + off, B3 + (size_t)(n0 + row) * K3_ + ldkc * 8);
        }
        CP_COMMIT();
    }

    const int lmat = lane >> 3, lr = lane & 7;

    for (int c = 0; c < NIT; ++c) {
        const int buf = c & 1;
        const uint32_t sa = buf ? sA1 : sA0;
        const uint32_t sb = buf ? sB1 : sB0;

        if (c + 1 < NIT) {
            const uint32_t na = buf ? sA0 : sA1;
            const uint32_t nb = buf ? sB0 : sB1;
            const int k0 = (c + 1) * 32;
#pragma unroll
            for (int l = 0; l < 2; ++l) {
                int row = ldrow + l * 64;
                uint32_t off = swz(row, ldkc);
                cp_async16(na + off, A3 + (size_t)(m0 + row) * K3_ + k0 + ldkc * 8);
                cp_async16(nb + off, B3 + (size_t)(n0 + row) * K3_ + k0 + ldkc * 8);
            }
            CP_COMMIT();
            asm volatile("cp.async.wait_group 1;");
        } else {
            asm volatile("cp.async.wait_group 0;");
        }
        __syncthreads();

#pragma unroll
        for (int s = 0; s < 2; ++s) {
            uint32_t a[4][4], b[4][2];
#pragma unroll
            for (int i = 0; i < 4; ++i) {
                int row = wm + i * 16 + (lmat & 1) * 8 + lr;
                int kc  = s * 2 + (lmat >> 1);
                ldsm4(a[i][0], a[i][1], a[i][2], a[i][3], sa + swz(row, kc));
            }
#pragma unroll
            for (int j = 0; j < 2; ++j) {
                int row = wn + j * 16 + (lmat >> 1) * 8 + lr;
                int kc  = s * 2 + (lmat & 1);
                uint32_t t0, t1, t2, t3;
                ldsm4(t0, t1, t2, t3, sb + swz(row, kc));
                b[j * 2][0] = t0;     b[j * 2][1] = t1;
                b[j * 2 + 1][0] = t2; b[j * 2 + 1][1] = t3;
            }
#pragma unroll
            for (int i = 0; i < 4; ++i)
#pragma unroll
                for (int j = 0; j < 4; ++j)
                    mma16816(acc[i][j], a[i], b[j]);
        }
        __syncthreads();
    }

    const int er = lane >> 2, ec = (lane & 3) * 2;
#pragma unroll
    for (int i = 0; i < 4; ++i) {
#pragma unroll
        for (int j = 0; j < 4; ++j) {
            size_t row = (size_t)(m0 + wm + i * 16 + er);
            int col = n0 + wn + j * 8 + ec;
            *(float2*)&C[row * N + col]       = make_float2(acc[i][j][0], acc[i][j][1]);
            *(float2*)&C[(row + 8) * N + col] = make_float2(acc[i][j][2], acc[i][j][3]);
        }
    }
}

// ---------------------------------------------------------------------------
// RoPE + head split -> bf16 hi/lo panels; V is written TRANSPOSED [bh][d][S].
// ---------------------------------------------------------------------------
__global__ void rope_split_bf(const float* __restrict__ qkv)
{
    int idx = blockIdx.x * blockDim.x + threadIdx.x;
    const int total = B_ * S_ * H_ * (HD_ / 2);
    if (idx >= total) return;

    int i = idx & 31;
    int t = idx >> 5;
    int h = t & (H_ - 1);
    t >>= 4;
    int s = t & (S_ - 1);
    int b = t >> 11;
    int bh = b * H_ + h;

    const float* row = qkv + (size_t)(b * S_ + s) * N_QKV;
    int col = h * HD_ + 2 * i;

    float q0 = row[col],          q1 = row[col + 1];
    float k0 = row[D_ + col],     k1 = row[D_ + col + 1];
    float v0 = row[2 * D_ + col], v1 = row[2 * D_ + col + 1];

    float inv_freq = (float)pow(10000.0, -(double)(2 * i) / (double)HD_);
    float ang = (float)s * inv_freq;
    float c = cosf(ang), sn = sinf(ang);

    float qr0 = q0 * c - q1 * sn, qr1 = q0 * sn + q1 * c;
    float kr0 = k0 * c - k1 * sn, kr1 = k0 * sn + k1 * c;

    size_t off = ((size_t)bh * S_ + s) * HD_ + 2 * i;
    __nv_bfloat16 hq0 = __float2bfloat16(qr0), hq1 = __float2bfloat16(qr1);
    __nv_bfloat16 hk0 = __float2bfloat16(kr0), hk1 = __float2bfloat16(kr1);
    g_qhi[off]     = hq0; g_qhi[off + 1] = hq1;
    g_qlo[off]     = __float2bfloat16(qr0 - __bfloat162float(hq0));
    g_qlo[off + 1] = __float2bfloat16(qr1 - __bfloat162float(hq1));
    g_khi[off]     = hk0; g_khi[off + 1] = hk1;
    g_klo[off]     = __float2bfloat16(kr0 - __bfloat162float(hk0));
    g_klo[off + 1] = __float2bfloat16(kr1 - __bfloat162float(hk1));

    // transposed V
    size_t tv0 = ((size_t)bh * HD_ + 2 * i) * S_ + s;
    size_t tv1 = ((size_t)bh * HD_ + 2 * i + 1) * S_ + s;
    __nv_bfloat16 hv0 = __float2bfloat16(v0), hv1 = __float2bfloat16(v1);
    g_vthi[tv0] = hv0;
    g_vthi[tv1] = hv1;
    g_vtlo[tv0] = __float2bfloat16(v0 - __bfloat162float(hv0));
    g_vtlo[tv1] = __float2bfloat16(v1 - __bfloat162float(hv1));
}

// ---------------------------------------------------------------------------
// HMMA flash attention. CTA: 128 queries x full key loop (64-key tiles).
// 4 warps x 32 query rows. QK^T and PV via mma.sync bf16 with 3-term splits.
// P stays in registers (C-frag == A-frag identity). Base-2 softmax, poly exp2.
// Output written as bf16x3 [hi|lo|hi] rows for the O-projection GEMM.
// ---------------------------------------------------------------------------
#define K2E 0.18033688011112042f   // 0.125 * log2(e)

__global__ __launch_bounds__(128) void flash_hmma(const int* __restrict__ pad,
                                                  __nv_bfloat16* __restrict__ O3)
{
    extern __shared__ __align__(128) char fsm[];
    __nv_bfloat16* Qs = (__nv_bfloat16*)fsm;               // [128][128] 32KB
    __nv_bfloat16* Ks = (__nv_bfloat16*)(fsm + 32768);     // [64][128]  16KB
    __nv_bfloat16* Vs = (__nv_bfloat16*)(fsm + 49152);     // [64][128]  16KB
    __shared__ float maddS[64];

    const uint32_t sQ = smem_u32(Qs), sK = smem_u32(Ks), sV = smem_u32(Vs);

    const int bh = blockIdx.y;
    const int b = bh >> 4;
    const int hh = bh & 15;
    const int qt = blockIdx.x;
    const int q0 = qt * 128;
    const int tid = threadIdx.x;
    const int wid = tid >> 5, lane = tid & 31;
    const int wm = wid * 32;
    const int lmat = lane >> 3, lr = lane & 7;

    const __nv_bfloat16* qh = g_qhi + (size_t)bh * S_ * HD_;
    const __nv_bfloat16* ql = g_qlo + (size_t)bh * S_ * HD_;
    const __nv_bfloat16* kh = g_khi + (size_t)bh * S_ * HD_;
    const __nv_bfloat16* kl = g_klo + (size_t)bh * S_ * HD_;
    const __nv_bfloat16* vh = g_vthi + (size_t)bh * HD_ * S_;
    const __nv_bfloat16* vl = g_vtlo + (size_t)bh * HD_ * S_;

    // ---- load Q tile (128 rows x 16 chunks: 0-7 hi, 8-15 lo)
#pragma unroll
    for (int l = 0; l < 16; ++l) {
        int slot = l * 128 + tid;        // 0..2047
        int row = slot >> 4, c = slot & 15;
        const __nv_bfloat16* src = (c < 8)
            ? qh + (size_t)(q0 + row) * HD_ + c * 8
            : ql + (size_t)(q0 + row) * HD_ + (c - 8) * 8;
        cp_async16(sQ + swz16(row, c), src);
    }
    CP_COMMIT();

    float m_[2][2], l_[2][2], oacc[2][8][4];
#pragma unroll
    for (int i = 0; i < 2; i++)
#pragma unroll
        for (int h2 = 0; h2 < 2; h2++) { m_[i][h2] = -1e30f; l_[i][h2] = 0.f; }
#pragma unroll
    for (int i = 0; i < 2; i++)
#pragma unroll
        for (int n = 0; n < 8; n++)
#pragma unroll
            for (int e = 0; e < 4; e++) oacc[i][n][e] = 0.f;

    const int nTiles = qt * 2 + 2;

    for (int kt = 0; kt < nTiles; ++kt) {
        const int kv0 = kt * 64;

        // ---- load K and Vt tiles (each 64 rows x 16 chunks)
#pragma unroll
        for (int l = 0; l < 8; ++l) {
            int slot = l * 128 + tid;    // 0..1023
            int row = slot >> 4, c = slot & 15;
            const __nv_bfloat16* srck = (c < 8)
                ? kh + (size_t)(kv0 + row) * HD_ + c * 8
                : kl + (size_t)(kv0 + row) * HD_ + (c - 8) * 8;
            cp_async16(sK + swz16(row, c), srck);
            const __nv_bfloat16* srcv = (c < 8)
                ? vh + (size_t)row * S_ + kv0 + c * 8
                : vl + (size_t)row * S_ + kv0 + (c - 8) * 8;
            cp_async16(sV + swz16(row, c), srcv);
        }
        CP_COMMIT();
        if (tid < 64)
            maddS[tid] = pad[b * S_ + kv0 + tid] ? 0.f : -1e30f;
        asm volatile("cp.async.wait_group 0;");
        __syncthreads();

        // warp-level causal skip: this warp's rows all < kv0 ?
        if (kv0 <= q0 + wm + 31) {
            // ---- S = Q K^T with 3-term split (12 k16 steps)
            float sacc[2][8][4];
#pragma unroll
            for (int i = 0; i < 2; i++)
#pragma unroll
                for (int n = 0; n < 8; n++)
#pragma unroll
                    for (int e = 0; e < 4; e++) sacc[i][n][e] = 0.f;

#pragma unroll
            for (int st = 0; st < 12; ++st) {
                int akc = (st < 4) ? st * 2 : (st < 8) ? 8 + (st - 4) * 2 : (st - 8) * 2;
                int bkc = (st < 8) ? (st & 3) * 2 : 8 + (st - 8) * 2;
                uint32_t a[2][4], bb[8][2];
#pragma unroll
                for (int i = 0; i < 2; ++i) {
                    int row = wm + i * 16 + (lmat & 1) * 8 + lr;
                    ldsm4(a[i][0], a[i][1], a[i][2], a[i][3],
                          sQ + swz16(row, akc + (lmat >> 1)));
                }
#pragma unroll
                for (int j = 0; j < 4; ++j) {
                    int row = j * 16 + (lmat >> 1) * 8 + lr;
                    uint32_t t0, t1, t2, t3;
                    ldsm4(t0, t1, t2, t3, sK + swz16(row, bkc + (lmat & 1)));
                    bb[j * 2][0] = t0;     bb[j * 2][1] = t1;
                    bb[j * 2 + 1][0] = t2; bb[j * 2 + 1][1] = t3;
                }
#pragma unroll
                for (int i = 0; i < 2; ++i)
#pragma unroll
                    for (int n = 0; n < 8; ++n)
                        mma16816(sacc[i][n], a[i], bb[n]);
            }

            // ---- mask + scale into base-2 domain
            const bool doCausal = (kv0 + 63 > q0 + wm);
#pragma unroll
            for (int n = 0; n < 8; ++n) {
                float md0 = maddS[n * 8 + (lane & 3) * 2];
                float md1 = maddS[n * 8 + (lane & 3) * 2 + 1];
#pragma unroll
                for (int i = 0; i < 2; ++i)
#pragma unroll
                    for (int e = 0; e < 4; ++e) {
                        float x = fmaf(sacc[i][n][e], K2E, (e & 1) ? md1 : md0);
                        if (doCausal) {
                            int key = kv0 + n * 8 + (lane & 3) * 2 + (e & 1);
                            int rw  = q0 + wm + i * 16 + (lane >> 2) + (e >> 1) * 8;
                            if (key > rw) x = -1e30f;
                        }
                        sacc[i][n][e] = x;
                    }
            }

            // ---- online softmax (per m-frag i, row-half h2)
#pragma unroll
            for (int i = 0; i < 2; ++i)
#pragma unroll
                for (int h2 = 0; h2 < 2; ++h2) {
                    float mx = -1e30f;
#pragma unroll
                    for (int n = 0; n < 8; ++n)
                        mx = fmaxf(mx, fmaxf(sacc[i][n][h2 * 2], sacc[i][n][h2 * 2 + 1]));
                    mx = fmaxf(mx, __shfl_xor_sync(0xffffffffu, mx, 1));
                    mx = fmaxf(mx, __shfl_xor_sync(0xffffffffu, mx, 2));
                    float mnew = fmaxf(m_[i][h2], mx);
                    float alpha = exp2p(m_[i][h2] - mnew);
                    float rs = 0.f;
#pragma unroll
                    for (int n = 0; n < 8; ++n) {
#pragma unroll
                        for (int e = h2 * 2; e < h2 * 2 + 2; ++e) {
                            float p = exp2p(sacc[i][n][e] - mnew);
                            sacc[i][n][e] = p;
                            rs += p;
                        }
                    }
                    rs += __shfl_xor_sync(0xffffffffu, rs, 1);
                    rs += __shfl_xor_sync(0xffffffffu, rs, 2);
                    l_[i][h2] = l_[i][h2] * alpha + rs;
                    m_[i][h2] = mnew;
#pragma unroll
                    for (int n = 0; n < 8; ++n) {
                        oacc[i][n][h2 * 2]     *= alpha;
                        oacc[i][n][h2 * 2 + 1] *= alpha;
                    }
                }

            // ---- O += P V (3-term split); A-frags built from sacc in registers
#pragma unroll
            for (int kk = 0; kk < 4; ++kk) {
                uint32_t aphi[2][4], aplo[2][4];
#pragma unroll
                for (int i = 0; i < 2; ++i) {
#pragma unroll
                    for (int half = 0; half < 2; ++half) {   // n-tile 2kk+half
                        int n = 2 * kk + half;
#pragma unroll
                        for (int pr = 0; pr < 2; ++pr) {     // reg pair (rows, rows+8)
                            float p0 = sacc[i][n][pr * 2];
                            float p1 = sacc[i][n][pr * 2 + 1];
                            uint32_t hi = pack_bf2(p0, p1);
                            __nv_bfloat162 h2v = *reinterpret_cast<__nv_bfloat162*>(&hi);
                            float l0 = p0 - __bfloat162float(h2v.x);
                            float l1 = p1 - __bfloat162float(h2v.y);
                            aphi[i][half * 2 + pr] = hi;
                            aplo[i][half * 2 + pr] = pack_bf2(l0, l1);
                        }
                    }
                }
                uint32_t bvh[8][2], bvl[8][2];
#pragma unroll
                for (int j = 0; j < 4; ++j) {
                    int row = j * 16 + (lmat >> 1) * 8 + lr;   // d rows
                    uint32_t t0, t1, t2, t3;
                    ldsm4(t0, t1, t2, t3, sV + swz16(row, kk * 2 + (lmat & 1)));
                    bvh[j * 2][0] = t0;     bvh[j * 2][1] = t1;
                    bvh[j * 2 + 1][0] = t2; bvh[j * 2 + 1][1] = t3;
                    ldsm4(t0, t1, t2, t3, sV + swz16(row, 8 + kk * 2 + (lmat & 1)));
                    bvl[j * 2][0] = t0;     bvl[j * 2][1] = t1;
                    bvl[j * 2 + 1][0] = t2; bvl[j * 2 + 1][1] = t3;
                }
#pragma unroll
                for (int i = 0; i < 2; ++i)
#pragma unroll
                    for (int nd = 0; nd < 8; ++nd) {
                        mma16816(oacc[i][nd], aphi[i], bvh[nd]);
                        mma16816(oacc[i][nd], aplo[i], bvh[nd]);
                        mma16816(oacc[i][nd], aphi[i], bvl[nd]);
                    }
            }
        }
        __syncthreads();   // all warps done with Ks/Vs before next tile load
    }

    // ---- epilogue: normalize, write bf16x3 [hi|lo|hi]
#pragma unroll
    for (int i = 0; i < 2; ++i) {
#pragma unroll
        for (int h2 = 0; h2 < 2; ++h2) {
            float inv = (l_[i][h2] > 0.f) ? (1.f / l_[i][h2]) : 0.f;
            int srow = q0 + wm + i * 16 + (lane >> 2) + h2 * 8;
            size_t token = (size_t)b * S_ + srow;
#pragma unroll
            for (int nd = 0; nd < 8; ++nd) {
                float v0 = oacc[i][nd][h2 * 2] * inv;
                float v1 = oacc[i][nd][h2 * 2 + 1] * inv;
                __nv_bfloat162 hi2 = __floats2bfloat162_rn(v0, v1);
                __nv_bfloat162 lo2 = __floats2bfloat162_rn(
                    v0 - __bfloat162float(hi2.x), v1 - __bfloat162float(hi2.y));
                size_t base = token * K3_ + hh * HD_ + nd * 8 + (lane & 3) * 2;
                *(__nv_bfloat162*)(O3 + base)        = hi2;
                *(__nv_bfloat162*)(O3 + base + 1024) = lo2;
                *(__nv_bfloat162*)(O3 + base + 2048) = hi2;
            }
        }
    }
}

// ---------------------------------------------------------------------------
// Launch
// ---------------------------------------------------------------------------
#define FLASH_SMEM 65536

extern "C" void kernel_launch(void* const* d_in, const int* in_sizes, int n_in,
                              void* d_out, int out_size)
{
    const float* x     = (const float*)d_in[0];
    const int*   pad   = (const int*)d_in[1];
    const float* w_qkv = (const float*)d_in[2];
    const float* w_o   = (const float*)d_in[3];
    float* out = (float*)d_out;

    float* qkv;
    __nv_bfloat16 *x3, *wqkv3, *wo3, *attn3;
    cudaGetSymbolAddress((void**)&qkv,   g_qkv);
    cudaGetSymbolAddress((void**)&x3,    g_x3);
    cudaGetSymbolAddress((void**)&wqkv3, g_wqkv3);
    cudaGetSymbolAddress((void**)&wo3,   g_wo3);
    cudaGetSymbolAddress((void**)&attn3, g_attn3);

    cudaFuncSetAttribute(flash_hmma, cudaFuncAttributeMaxDynamicSharedMemorySize,
                         FLASH_SMEM);

    // 0) fp32 -> bf16x3 splits
    {
        int txc = M_ * D_;
        conv_bf16x3<<<(txc + 255) / 256, 256>>>(x, x3, txc, 1);
        int tw = N_QKV * D_;
        conv_bf16x3<<<(tw + 255) / 256, 256>>>(w_qkv, wqkv3, tw, 0);
        int to = D_ * D_;
        conv_bf16x3<<<(to + 255) / 256, 256>>>(w_o, wo3, to, 0);
    }

    // 1) QKV projection (HMMA)
    {
        dim3 grid(N_QKV / 128, M_ / 128);
        gemm_hmma<<<grid, 256>>>(x3, wqkv3, qkv, N_QKV);
    }

    // 2) RoPE + head split into bf16 hi/lo panels (V transposed)
    {
        int total = B_ * S_ * H_ * (HD_ / 2);
        rope_split_bf<<<(total + 255) / 256, 256>>>(qkv);
    }

    // 3) HMMA flash attention
    {
        dim3 grid(S_ / 128, B_ * H_);
        flash_hmma<<<grid, 128, FLASH_SMEM>>>(pad, attn3);
    }

    // 4) Output projection (HMMA) -> d_out (fp32)
    {
        dim3 grid(D_ / 128, M_ / 128);
        gemm_hmma<<<grid, 256>>>(attn3, wo3, out, D_);
    }
}

// round 10
// speedup vs baseline: 2.2956x; 1.0421x over previous
#include <cuda_runtime.h>
#include <cuda_bf16.h>
#include <math.h>
#include <stdint.h>

// Problem constants
#define B_  4
#define S_  2048
#define D_  1024
#define H_  16
#define HD_ 64
#define M_  (B_ * S_)          // 8192
#define N_QKV (3 * D_)         // 3072
#define K3_ 3072               // 3x split K for bf16x3 GEMMs
#define NIT 96                 // K3_ / 32 mainloop iterations

// ---------------------------------------------------------------------------
// Helpers (sm_80+ baseline features only: mma.sync / ldmatrix / cp.async)
// ---------------------------------------------------------------------------
__device__ __forceinline__ uint32_t smem_u32(const void* p) {
    uint32_t a;
    asm("{ .reg .u64 t; cvta.to.shared.u64 t, %1; cvt.u32.u64 %0, t; }" : "=r"(a) : "l"(p));
    return a;
}
__device__ __forceinline__ void cp_async16(uint32_t s, const void* g) {
    asm volatile("cp.async.cg.shared.global [%0], [%1], 16;" :: "r"(s), "l"(g));
}
#define CP_COMMIT() asm volatile("cp.async.commit_group;")

__device__ __forceinline__ void ldsm4(uint32_t& r0, uint32_t& r1, uint32_t& r2,
                                      uint32_t& r3, uint32_t addr) {
    asm volatile("ldmatrix.sync.aligned.m8n8.x4.shared.b16 {%0,%1,%2,%3}, [%4];"
                 : "=r"(r0), "=r"(r1), "=r"(r2), "=r"(r3) : "r"(addr));
}
__device__ __forceinline__ void mma16816(float* c, const uint32_t* a, const uint32_t* b) {
    asm volatile(
        "mma.sync.aligned.m16n8k16.row.col.f32.bf16.bf16.f32 "
        "{%0,%1,%2,%3}, {%4,%5,%6,%7}, {%8,%9}, {%0,%1,%2,%3};"
        : "+f"(c[0]), "+f"(c[1]), "+f"(c[2]), "+f"(c[3])
        : "r"(a[0]), "r"(a[1]), "r"(a[2]), "r"(a[3]), "r"(b[0]), "r"(b[1]));
}

// MUFU exp2: 1 instruction, runs on its own pipe; ftz underflows big-neg to 0
__device__ __forceinline__ float ex2(float x) {
    float y;
    asm("ex2.approx.ftz.f32 %0, %1;" : "=f"(y) : "f"(x));
    return y;
}

__device__ __forceinline__ uint32_t pack_bf2(float a, float b) {
    __nv_bfloat162 t = __floats2bfloat162_rn(a, b);   // .x = a (low)
    return *reinterpret_cast<uint32_t*>(&t);
}

// Swizzled byte offset, 256B rows, 16B chunk index c (0..15); xor low 3 bits
__device__ __forceinline__ uint32_t swz16(int row, int c) {
    return (uint32_t)(row * 256 + ((c ^ (row & 7)) << 4));
}
// 128B-row swizzle for the GEMM
__device__ __forceinline__ uint32_t swz(int row, int kc) {
    return (uint32_t)(row * 64 + ((kc ^ ((row >> 1) & 3)) << 4));
}

// ---------------------------------------------------------------------------
// Scratch (device globals: no allocation allowed)
// ---------------------------------------------------------------------------
__device__ float         g_qkv[(size_t)M_ * N_QKV];
__device__ __nv_bfloat16 g_x3[(size_t)M_ * K3_];             // [hi|lo|hi]
__device__ __nv_bfloat16 g_wqkv3[(size_t)N_QKV * K3_];       // [hi|hi|lo]
__device__ __nv_bfloat16 g_wo3[(size_t)D_ * K3_];            // [hi|hi|lo]
__device__ __nv_bfloat16 g_attn3[(size_t)M_ * K3_];          // [hi|lo|hi]
#define BHSD ((size_t)B_ * H_ * S_ * HD_)
__device__ __nv_bfloat16 g_qhi[BHSD], g_qlo[BHSD];           // [bh][s][64]
__device__ __nv_bfloat16 g_khi[BHSD], g_klo[BHSD];           // [bh][s][64]
__device__ __nv_bfloat16 g_vthi[BHSD], g_vtlo[BHSD];         // [bh][64][S]

// ---------------------------------------------------------------------------
// fp32 -> bf16x3 split
// ---------------------------------------------------------------------------
__global__ void conv_bf16x3(const float* __restrict__ src,
                            __nv_bfloat16* __restrict__ dst,
                            int total, int a_type)
{
    int idx = blockIdx.x * blockDim.x + threadIdx.x;
    if (idx >= total) return;
    int row = idx >> 10;
    int col = idx & 1023;
    float a = src[idx];
    __nv_bfloat16 hi = __float2bfloat16(a);
    __nv_bfloat16 lo = __float2bfloat16(a - __bfloat162float(hi));
    size_t base = (size_t)row * K3_;
    dst[base + col] = hi;
    dst[base + 1024 + col] = a_type ? lo : hi;
    dst[base + 2048 + col] = a_type ? hi : lo;
}

// ---------------------------------------------------------------------------
// HMMA bf16 GEMM (verified, unchanged)
// ---------------------------------------------------------------------------
__global__ __launch_bounds__(256) void gemm_hmma(
    const __nv_bfloat16* __restrict__ A3,
    const __nv_bfloat16* __restrict__ B3,
    float* __restrict__ C, int N)
{
    __shared__ __align__(128) __nv_bfloat16 As[2][128 * 32];
    __shared__ __align__(128) __nv_bfloat16 Bs[2][128 * 32];

    const int tid = threadIdx.x;
    const int wid = tid >> 5, lane = tid & 31;
    const int m0 = blockIdx.y * 128, n0 = blockIdx.x * 128;
    const int wm = (wid & 1) * 64;
    const int wn = (wid >> 1) * 32;

    const uint32_t sA0 = smem_u32(As[0]), sA1 = smem_u32(As[1]);
    const uint32_t sB0 = smem_u32(Bs[0]), sB1 = smem_u32(Bs[1]);

    float acc[4][4][4];
#pragma unroll
    for (int i = 0; i < 4; i++)
#pragma unroll
        for (int j = 0; j < 4; j++)
#pragma unroll
            for (int e = 0; e < 4; e++) acc[i][j][e] = 0.f;

    const int ldrow = tid >> 2;
    const int ldkc  = tid & 3;

    {
#pragma unroll
        for (int l = 0; l < 2; ++l) {
            int row = ldrow + l * 64;
            uint32_t off = swz(row, ldkc);
            cp_async16(sA0 + off, A3 + (size_t)(m0 + row) * K3_ + ldkc * 8);
            cp_async16(sB0 + off, B3 + (size_t)(n0 + row) * K3_ + ldkc * 8);
        }
        CP_COMMIT();
    }

    const int lmat = lane >> 3, lr = lane & 7;

    for (int c = 0; c < NIT; ++c) {
        const int buf = c & 1;
        const uint32_t sa = buf ? sA1 : sA0;
        const uint32_t sb = buf ? sB1 : sB0;

        if (c + 1 < NIT) {
            const uint32_t na = buf ? sA0 : sA1;
            const uint32_t nb = buf ? sB0 : sB1;
            const int k0 = (c + 1) * 32;
#pragma unroll
            for (int l = 0; l < 2; ++l) {
                int row = ldrow + l * 64;
                uint32_t off = swz(row, ldkc);
                cp_async16(na + off, A3 + (size_t)(m0 + row) * K3_ + k0 + ldkc * 8);
                cp_async16(nb + off, B3 + (size_t)(n0 + row) * K3_ + k0 + ldkc * 8);
            }
            CP_COMMIT();
            asm volatile("cp.async.wait_group 1;");
        } else {
            asm volatile("cp.async.wait_group 0;");
        }
        __syncthreads();

#pragma unroll
        for (int s = 0; s < 2; ++s) {
            uint32_t a[4][4], b[4][2];
#pragma unroll
            for (int i = 0; i < 4; ++i) {
                int row = wm + i * 16 + (lmat & 1) * 8 + lr;
                int kc  = s * 2 + (lmat >> 1);
                ldsm4(a[i][0], a[i][1], a[i][2], a[i][3], sa + swz(row, kc));
            }
#pragma unroll
            for (int j = 0; j < 2; ++j) {
                int row = wn + j * 16 + (lmat >> 1) * 8 + lr;
                int kc  = s * 2 + (lmat & 1);
                uint32_t t0, t1, t2, t3;
                ldsm4(t0, t1, t2, t3, sb + swz(row, kc));
                b[j * 2][0] = t0;     b[j * 2][1] = t1;
                b[j * 2 + 1][0] = t2; b[j * 2 + 1][1] = t3;
            }
#pragma unroll
            for (int i = 0; i < 4; ++i)
#pragma unroll
                for (int j = 0; j < 4; ++j)
                    mma16816(acc[i][j], a[i], b[j]);
        }
        __syncthreads();
    }

    const int er = lane >> 2, ec = (lane & 3) * 2;
#pragma unroll
    for (int i = 0; i < 4; ++i) {
#pragma unroll
        for (int j = 0; j < 4; ++j) {
            size_t row = (size_t)(m0 + wm + i * 16 + er);
            int col = n0 + wn + j * 8 + ec;
            *(float2*)&C[row * N + col]       = make_float2(acc[i][j][0], acc[i][j][1]);
            *(float2*)&C[(row + 8) * N + col] = make_float2(acc[i][j][2], acc[i][j][3]);
        }
    }
}

// ---------------------------------------------------------------------------
// RoPE + head split -> bf16 hi/lo panels; V written TRANSPOSED [bh][d][S].
// ---------------------------------------------------------------------------
__global__ void rope_split_bf(const float* __restrict__ qkv)
{
    int idx = blockIdx.x * blockDim.x + threadIdx.x;
    const int total = B_ * S_ * H_ * (HD_ / 2);
    if (idx >= total) return;

    int i = idx & 31;
    int t = idx >> 5;
    int h = t & (H_ - 1);
    t >>= 4;
    int s = t & (S_ - 1);
    int b = t >> 11;
    int bh = b * H_ + h;

    const float* row = qkv + (size_t)(b * S_ + s) * N_QKV;
    int col = h * HD_ + 2 * i;

    float q0 = row[col],          q1 = row[col + 1];
    float k0 = row[D_ + col],     k1 = row[D_ + col + 1];
    float v0 = row[2 * D_ + col], v1 = row[2 * D_ + col + 1];

    float inv_freq = (float)pow(10000.0, -(double)(2 * i) / (double)HD_);
    float ang = (float)s * inv_freq;
    float c = cosf(ang), sn = sinf(ang);

    float qr0 = q0 * c - q1 * sn, qr1 = q0 * sn + q1 * c;
    float kr0 = k0 * c - k1 * sn, kr1 = k0 * sn + k1 * c;

    size_t off = ((size_t)bh * S_ + s) * HD_ + 2 * i;
    __nv_bfloat16 hq0 = __float2bfloat16(qr0), hq1 = __float2bfloat16(qr1);
    __nv_bfloat16 hk0 = __float2bfloat16(kr0), hk1 = __float2bfloat16(kr1);
    g_qhi[off]     = hq0; g_qhi[off + 1] = hq1;
    g_qlo[off]     = __float2bfloat16(qr0 - __bfloat162float(hq0));
    g_qlo[off + 1] = __float2bfloat16(qr1 - __bfloat162float(hq1));
    g_khi[off]     = hk0; g_khi[off + 1] = hk1;
    g_klo[off]     = __float2bfloat16(kr0 - __bfloat162float(hk0));
    g_klo[off + 1] = __float2bfloat16(kr1 - __bfloat162float(hk1));

    size_t tv0 = ((size_t)bh * HD_ + 2 * i) * S_ + s;
    size_t tv1 = ((size_t)bh * HD_ + 2 * i + 1) * S_ + s;
    __nv_bfloat16 hv0 = __float2bfloat16(v0), hv1 = __float2bfloat16(v1);
    g_vthi[tv0] = hv0;
    g_vthi[tv1] = hv1;
    g_vtlo[tv0] = __float2bfloat16(v0 - __bfloat162float(hv0));
    g_vtlo[tv1] = __float2bfloat16(v1 - __bfloat162float(hv1));
}

// ---------------------------------------------------------------------------
// HMMA flash attention v2: MUFU ex2 softmax, double-buffered K/V,
// P packed once per tile, V-frags loaded per nd-pair.
// Mask value -3e38: ex2(masked - m) underflows to 0 with no compare.
// ---------------------------------------------------------------------------
#define K2E 0.18033688011112042f   // 0.125 * log2(e)
#define MASKV -3.0e38f

__global__ __launch_bounds__(128) void flash_hmma(const int* __restrict__ pad,
                                                  __nv_bfloat16* __restrict__ O3)
{
    extern __shared__ __align__(128) char fsm[];
    const uint32_t sQ  = smem_u32(fsm);          // [128][256B] 32KB
    const uint32_t sK0 = sQ + 32768;             // [64][256B]  16KB
    const uint32_t sV0 = sQ + 49152;
    const uint32_t sK1 = sQ + 65536;
    const uint32_t sV1 = sQ + 81920;
    __shared__ float maddS[2][64];

    const int bh = blockIdx.y;
    const int b = bh >> 4;
    const int hh = bh & 15;
    const int qt = blockIdx.x;
    const int q0 = qt * 128;
    const int tid = threadIdx.x;
    const int wid = tid >> 5, lane = tid & 31;
    const int wm = wid * 32;
    const int lmat = lane >> 3, lr = lane & 7;

    const __nv_bfloat16* qh = g_qhi + (size_t)bh * S_ * HD_;
    const __nv_bfloat16* ql = g_qlo + (size_t)bh * S_ * HD_;
    const __nv_bfloat16* kh = g_khi + (size_t)bh * S_ * HD_;
    const __nv_bfloat16* kl = g_klo + (size_t)bh * S_ * HD_;
    const __nv_bfloat16* vh = g_vthi + (size_t)bh * HD_ * S_;
    const __nv_bfloat16* vl = g_vtlo + (size_t)bh * HD_ * S_;

    // ---- prologue: Q tile (group), then K/V tile 0 (group)
#pragma unroll
    for (int l = 0; l < 16; ++l) {
        int slot = l * 128 + tid;
        int row = slot >> 4, c = slot & 15;
        const __nv_bfloat16* src = (c < 8)
            ? qh + (size_t)(q0 + row) * HD_ + c * 8
            : ql + (size_t)(q0 + row) * HD_ + (c - 8) * 8;
        cp_async16(sQ + swz16(row, c), src);
    }
    CP_COMMIT();
#pragma unroll
    for (int l = 0; l < 8; ++l) {
        int slot = l * 128 + tid;
        int row = slot >> 4, c = slot & 15;
        const __nv_bfloat16* srck = (c < 8)
            ? kh + (size_t)row * HD_ + c * 8
            : kl + (size_t)row * HD_ + (c - 8) * 8;
        cp_async16(sK0 + swz16(row, c), srck);
        const __nv_bfloat16* srcv = (c < 8)
            ? vh + (size_t)row * S_ + c * 8
            : vl + (size_t)row * S_ + (c - 8) * 8;
        cp_async16(sV0 + swz16(row, c), srcv);
    }
    CP_COMMIT();
    if (tid < 64)
        maddS[0][tid] = pad[b * S_ + tid] ? 0.f : MASKV;

    float m_[2][2], l_[2][2], oacc[2][8][4];
#pragma unroll
    for (int i = 0; i < 2; i++)
#pragma unroll
        for (int h2 = 0; h2 < 2; h2++) { m_[i][h2] = -1e30f; l_[i][h2] = 0.f; }
#pragma unroll
    for (int i = 0; i < 2; i++)
#pragma unroll
        for (int n = 0; n < 8; n++)
#pragma unroll
            for (int e = 0; e < 4; e++) oacc[i][n][e] = 0.f;

    const int nTiles = qt * 2 + 2;

    for (int kt = 0; kt < nTiles; ++kt) {
        const int buf = kt & 1;
        const uint32_t sK = buf ? sK1 : sK0;
        const uint32_t sV = buf ? sV1 : sV0;

        // prefetch tile kt+1 into the other buffer
        if (kt + 1 < nTiles) {
            const uint32_t nK = buf ? sK0 : sK1;
            const uint32_t nV = buf ? sV0 : sV1;
            const int nv0 = (kt + 1) * 64;
#pragma unroll
            for (int l = 0; l < 8; ++l) {
                int slot = l * 128 + tid;
                int row = slot >> 4, c = slot & 15;
                const __nv_bfloat16* srck = (c < 8)
                    ? kh + (size_t)(nv0 + row) * HD_ + c * 8
                    : kl + (size_t)(nv0 + row) * HD_ + (c - 8) * 8;
                cp_async16(nK + swz16(row, c), srck);
                const __nv_bfloat16* srcv = (c < 8)
                    ? vh + (size_t)row * S_ + nv0 + c * 8
                    : vl + (size_t)row * S_ + nv0 + (c - 8) * 8;
                cp_async16(nV + swz16(row, c), srcv);
            }
            CP_COMMIT();
            if (tid < 64)
                maddS[(kt + 1) & 1][tid] = pad[b * S_ + nv0 + tid] ? 0.f : MASKV;
            asm volatile("cp.async.wait_group 1;");
        } else {
            asm volatile("cp.async.wait_group 0;");
        }
        __syncthreads();

        const int kv0 = kt * 64;
        if (kv0 <= q0 + wm + 31) {     // warp-level causal skip
            // ---- S = Q K^T, 3-term split (12 k16 steps)
            float sacc[2][8][4];
#pragma unroll
            for (int i = 0; i < 2; i++)
#pragma unroll
                for (int n = 0; n < 8; n++)
#pragma unroll
                    for (int e = 0; e < 4; e++) sacc[i][n][e] = 0.f;

#pragma unroll
            for (int st = 0; st < 12; ++st) {
                int akc = (st < 4) ? st * 2 : (st < 8) ? 8 + (st - 4) * 2 : (st - 8) * 2;
                int bkc = (st < 8) ? (st & 3) * 2 : 8 + (st - 8) * 2;
                uint32_t a[2][4], bb[8][2];
#pragma unroll
                for (int i = 0; i < 2; ++i) {
                    int row = wm + i * 16 + (lmat & 1) * 8 + lr;
                    ldsm4(a[i][0], a[i][1], a[i][2], a[i][3],
                          sQ + swz16(row, akc + (lmat >> 1)));
                }
#pragma unroll
                for (int j = 0; j < 4; ++j) {
                    int row = j * 16 + (lmat >> 1) * 8 + lr;
                    uint32_t t0, t1, t2, t3;
                    ldsm4(t0, t1, t2, t3, sK + swz16(row, bkc + (lmat & 1)));
                    bb[j * 2][0] = t0;     bb[j * 2][1] = t1;
                    bb[j * 2 + 1][0] = t2; bb[j * 2 + 1][1] = t3;
                }
#pragma unroll
                for (int i = 0; i < 2; ++i)
#pragma unroll
                    for (int n = 0; n < 8; ++n)
                        mma16816(sacc[i][n], a[i], bb[n]);
            }

            // ---- mask + scale into base-2 domain
            const bool doCausal = (kv0 + 63 > q0 + wm);
#pragma unroll
            for (int n = 0; n < 8; ++n) {
                float md0 = maddS[buf][n * 8 + (lane & 3) * 2];
                float md1 = maddS[buf][n * 8 + (lane & 3) * 2 + 1];
#pragma unroll
                for (int i = 0; i < 2; ++i)
#pragma unroll
                    for (int e = 0; e < 4; ++e) {
                        float x = fmaf(sacc[i][n][e], K2E, (e & 1) ? md1 : md0);
                        if (doCausal) {
                            int key = kv0 + n * 8 + (lane & 3) * 2 + (e & 1);
                            int rw  = q0 + wm + i * 16 + (lane >> 2) + (e >> 1) * 8;
                            if (key > rw) x = MASKV;
                        }
                        sacc[i][n][e] = x;
                    }
            }

            // ---- online softmax (MUFU ex2)
#pragma unroll
            for (int i = 0; i < 2; ++i)
#pragma unroll
                for (int h2 = 0; h2 < 2; ++h2) {
                    float mx = MASKV;
#pragma unroll
                    for (int n = 0; n < 8; ++n)
                        mx = fmaxf(mx, fmaxf(sacc[i][n][h2 * 2], sacc[i][n][h2 * 2 + 1]));
                    mx = fmaxf(mx, __shfl_xor_sync(0xffffffffu, mx, 1));
                    mx = fmaxf(mx, __shfl_xor_sync(0xffffffffu, mx, 2));
                    float mnew = fmaxf(m_[i][h2], mx);
                    float alpha = ex2(m_[i][h2] - mnew);
                    float rs = 0.f;
#pragma unroll
                    for (int n = 0; n < 8; ++n) {
#pragma unroll
                        for (int e = h2 * 2; e < h2 * 2 + 2; ++e) {
                            float p = ex2(sacc[i][n][e] - mnew);
                            sacc[i][n][e] = p;
                            rs += p;
                        }
                    }
                    rs += __shfl_xor_sync(0xffffffffu, rs, 1);
                    rs += __shfl_xor_sync(0xffffffffu, rs, 2);
                    l_[i][h2] = l_[i][h2] * alpha + rs;
                    m_[i][h2] = mnew;
#pragma unroll
                    for (int n = 0; n < 8; ++n) {
                        oacc[i][n][h2 * 2]     *= alpha;
                        oacc[i][n][h2 * 2 + 1] *= alpha;
                    }
                }

            // ---- pack P once: phi/plo[i][kk][4] (sacc dies here)
            uint32_t phi[2][4][4], plo[2][4][4];
#pragma unroll
            for (int i = 0; i < 2; ++i)
#pragma unroll
                for (int n = 0; n < 8; ++n) {
                    int kk = n >> 1, half = n & 1;
#pragma unroll
                    for (int pr = 0; pr < 2; ++pr) {
                        float p0 = sacc[i][n][pr * 2];
                        float p1 = sacc[i][n][pr * 2 + 1];
                        uint32_t hi = pack_bf2(p0, p1);
                        __nv_bfloat162 h2v = *reinterpret_cast<__nv_bfloat162*>(&hi);
                        phi[i][kk][half * 2 + pr] = hi;
                        plo[i][kk][half * 2 + pr] =
                            pack_bf2(p0 - __bfloat162float(h2v.x),
                                     p1 - __bfloat162float(h2v.y));
                    }
                }

            // ---- O += P V (3-term); V-frags per nd-pair
#pragma unroll
            for (int kk = 0; kk < 4; ++kk) {
#pragma unroll
                for (int g = 0; g < 4; ++g) {
                    int row = g * 16 + (lmat >> 1) * 8 + lr;
                    uint32_t t0, t1, t2, t3, u0, u1, u2, u3;
                    ldsm4(t0, t1, t2, t3, sV + swz16(row, kk * 2 + (lmat & 1)));
                    ldsm4(u0, u1, u2, u3, sV + swz16(row, 8 + kk * 2 + (lmat & 1)));
                    uint32_t bh0[2] = {t0, t1}, bh1[2] = {t2, t3};
                    uint32_t bl0[2] = {u0, u1}, bl1[2] = {u2, u3};
#pragma unroll
                    for (int i = 0; i < 2; ++i) {
                        mma16816(oacc[i][2 * g],     phi[i][kk], bh0);
                        mma16816(oacc[i][2 * g],     plo[i][kk], bh0);
                        mma16816(oacc[i][2 * g],     phi[i][kk], bl0);
                        mma16816(oacc[i][2 * g + 1], phi[i][kk], bh1);
                        mma16816(oacc[i][2 * g + 1], plo[i][kk], bh1);
                        mma16816(oacc[i][2 * g + 1], phi[i][kk], bl1);
                    }
                }
            }
        }
        __syncthreads();
    }

    // ---- epilogue: normalize, write bf16x3 [hi|lo|hi]
#pragma unroll
    for (int i = 0; i < 2; ++i) {
#pragma unroll
        for (int h2 = 0; h2 < 2; ++h2) {
            float inv = (l_[i][h2] > 0.f) ? (1.f / l_[i][h2]) : 0.f;
            int srow = q0 + wm + i * 16 + (lane >> 2) + h2 * 8;
            size_t token = (size_t)b * S_ + srow;
#pragma unroll
            for (int nd = 0; nd < 8; ++nd) {
                float v0 = oacc[i][nd][h2 * 2] * inv;
                float v1 = oacc[i][nd][h2 * 2 + 1] * inv;
                __nv_bfloat162 hi2 = __floats2bfloat162_rn(v0, v1);
                __nv_bfloat162 lo2 = __floats2bfloat162_rn(
                    v0 - __bfloat162float(hi2.x), v1 - __bfloat162float(hi2.y));
                size_t base = token * K3_ + hh * HD_ + nd * 8 + (lane & 3) * 2;
                *(__nv_bfloat162*)(O3 + base)        = hi2;
                *(__nv_bfloat162*)(O3 + base + 1024) = lo2;
                *(__nv_bfloat162*)(O3 + base + 2048) = hi2;
            }
        }
    }
}

// ---------------------------------------------------------------------------
// Launch
// ---------------------------------------------------------------------------
#define FLASH_SMEM 98304   // Q 32KB + 2 x (K 16KB + V 16KB)

extern "C" void kernel_launch(void* const* d_in, const int* in_sizes, int n_in,
                              void* d_out, int out_size)
{
    const float* x     = (const float*)d_in[0];
    const int*   pad   = (const int*)d_in[1];
    const float* w_qkv = (const float*)d_in[2];
    const float* w_o   = (const float*)d_in[3];
    float* out = (float*)d_out;

    float* qkv;
    __nv_bfloat16 *x3, *wqkv3, *wo3, *attn3;
    cudaGetSymbolAddress((void**)&qkv,   g_qkv);
    cudaGetSymbolAddress((void**)&x3,    g_x3);
    cudaGetSymbolAddress((void**)&wqkv3, g_wqkv3);
    cudaGetSymbolAddress((void**)&wo3,   g_wo3);
    cudaGetSymbolAddress((void**)&attn3, g_attn3);

    cudaFuncSetAttribute(flash_hmma, cudaFuncAttributeMaxDynamicSharedMemorySize,
                         FLASH_SMEM);

    // 0) fp32 -> bf16x3 splits
    {
        int txc = M_ * D_;
        conv_bf16x3<<<(txc + 255) / 256, 256>>>(x, x3, txc, 1);
        int tw = N_QKV * D_;
        conv_bf16x3<<<(tw + 255) / 256, 256>>>(w_qkv, wqkv3, tw, 0);
        int to = D_ * D_;
        conv_bf16x3<<<(to + 255) / 256, 256>>>(w_o, wo3, to, 0);
    }

    // 1) QKV projection (HMMA)
    {
        dim3 grid(N_QKV / 128, M_ / 128);
        gemm_hmma<<<grid, 256>>>(x3, wqkv3, qkv, N_QKV);
    }

    // 2) RoPE + head split into bf16 hi/lo panels (V transposed)
    {
        int total = B_ * S_ * H_ * (HD_ / 2);
        rope_split_bf<<<(total + 255) / 256, 256>>>(qkv);
    }

    // 3) HMMA flash attention v2
    {
        dim3 grid(S_ / 128, B_ * H_);
        flash_hmma<<<grid, 128, FLASH_SMEM>>>(pad, attn3);
    }

    // 4) Output projection (HMMA) -> d_out (fp32)
    {
        dim3 grid(D_ / 128, M_ / 128);
        gemm_hmma<<<grid, 256>>>(attn3, wo3, out, D_);
    }
}

// round 11
// speedup vs baseline: 2.3150x; 1.0085x over previous
#include <cuda_runtime.h>
#include <cuda_bf16.h>
#include <math.h>
#include <stdint.h>

// Problem constants
#define B_  4
#define S_  2048
#define D_  1024
#define H_  16
#define HD_ 64
#define M_  (B_ * S_)          // 8192
#define N_QKV (3 * D_)         // 3072
#define K3_ 3072               // 3x split K for bf16x3 GEMMs
#define NIT 96                 // K3_ / 32 mainloop iterations

// ---------------------------------------------------------------------------
// Helpers (sm_80+ baseline features only: mma.sync / ldmatrix / cp.async)
// ---------------------------------------------------------------------------
__device__ __forceinline__ uint32_t smem_u32(const void* p) {
    uint32_t a;
    asm("{ .reg .u64 t; cvta.to.shared.u64 t, %1; cvt.u32.u64 %0, t; }" : "=r"(a) : "l"(p));
    return a;
}
__device__ __forceinline__ void cp_async16(uint32_t s, const void* g) {
    asm volatile("cp.async.cg.shared.global [%0], [%1], 16;" :: "r"(s), "l"(g));
}
#define CP_COMMIT() asm volatile("cp.async.commit_group;")

__device__ __forceinline__ void ldsm4(uint32_t& r0, uint32_t& r1, uint32_t& r2,
                                      uint32_t& r3, uint32_t addr) {
    asm volatile("ldmatrix.sync.aligned.m8n8.x4.shared.b16 {%0,%1,%2,%3}, [%4];"
                 : "=r"(r0), "=r"(r1), "=r"(r2), "=r"(r3) : "r"(addr));
}
__device__ __forceinline__ void mma16816(float* c, const uint32_t* a, const uint32_t* b) {
    asm volatile(
        "mma.sync.aligned.m16n8k16.row.col.f32.bf16.bf16.f32 "
        "{%0,%1,%2,%3}, {%4,%5,%6,%7}, {%8,%9}, {%0,%1,%2,%3};"
        : "+f"(c[0]), "+f"(c[1]), "+f"(c[2]), "+f"(c[3])
        : "r"(a[0]), "r"(a[1]), "r"(a[2]), "r"(a[3]), "r"(b[0]), "r"(b[1]));
}

// MUFU exp2: 1 instruction on its own pipe; ftz underflows big-neg to 0
__device__ __forceinline__ float ex2(float x) {
    float y;
    asm("ex2.approx.ftz.f32 %0, %1;" : "=f"(y) : "f"(x));
    return y;
}

__device__ __forceinline__ uint32_t pack_bf2(float a, float b) {
    __nv_bfloat162 t = __floats2bfloat162_rn(a, b);   // .x = a (low)
    return *reinterpret_cast<uint32_t*>(&t);
}

// Swizzled byte offset, 256B rows, 16B chunk index c (0..15); xor low 3 bits
__device__ __forceinline__ uint32_t swz16(int row, int c) {
    return (uint32_t)(row * 256 + ((c ^ (row & 7)) << 4));
}
// 128B-row swizzle for the GEMM
__device__ __forceinline__ uint32_t swz(int row, int kc) {
    return (uint32_t)(row * 64 + ((kc ^ ((row >> 1) & 3)) << 4));
}

// ---------------------------------------------------------------------------
// Scratch (device globals: no allocation allowed)
// ---------------------------------------------------------------------------
__device__ float         g_qkv[(size_t)M_ * N_QKV];
__device__ __nv_bfloat16 g_x3[(size_t)M_ * K3_];             // [hi|lo|hi]
__device__ __nv_bfloat16 g_wqkv3[(size_t)N_QKV * K3_];       // [hi|hi|lo]
__device__ __nv_bfloat16 g_wo3[(size_t)D_ * K3_];            // [hi|hi|lo]
__device__ __nv_bfloat16 g_attn3[(size_t)M_ * K3_];          // [hi|lo|hi]
#define BHSD ((size_t)B_ * H_ * S_ * HD_)
__device__ __nv_bfloat16 g_qhi[BHSD], g_qlo[BHSD];           // [bh][s][64]
__device__ __nv_bfloat16 g_khi[BHSD], g_klo[BHSD];           // [bh][s][64]
__device__ __nv_bfloat16 g_vthi[BHSD], g_vtlo[BHSD];         // [bh][64][S]

// ---------------------------------------------------------------------------
// fp32 -> bf16x3 split
// ---------------------------------------------------------------------------
__global__ void conv_bf16x3(const float* __restrict__ src,
                            __nv_bfloat16* __restrict__ dst,
                            int total, int a_type)
{
    int idx = blockIdx.x * blockDim.x + threadIdx.x;
    if (idx >= total) return;
    int row = idx >> 10;
    int col = idx & 1023;
    float a = src[idx];
    __nv_bfloat16 hi = __float2bfloat16(a);
    __nv_bfloat16 lo = __float2bfloat16(a - __bfloat162float(hi));
    size_t base = (size_t)row * K3_;
    dst[base + col] = hi;
    dst[base + 1024 + col] = a_type ? lo : hi;
    dst[base + 2048 + col] = a_type ? hi : lo;
}

// ---------------------------------------------------------------------------
// HMMA bf16 GEMM (verified, unchanged)
// ---------------------------------------------------------------------------
__global__ __launch_bounds__(256) void gemm_hmma(
    const __nv_bfloat16* __restrict__ A3,
    const __nv_bfloat16* __restrict__ B3,
    float* __restrict__ C, int N)
{
    __shared__ __align__(128) __nv_bfloat16 As[2][128 * 32];
    __shared__ __align__(128) __nv_bfloat16 Bs[2][128 * 32];

    const int tid = threadIdx.x;
    const int wid = tid >> 5, lane = tid & 31;
    const int m0 = blockIdx.y * 128, n0 = blockIdx.x * 128;
    const int wm = (wid & 1) * 64;
    const int wn = (wid >> 1) * 32;

    const uint32_t sA0 = smem_u32(As[0]), sA1 = smem_u32(As[1]);
    const uint32_t sB0 = smem_u32(Bs[0]), sB1 = smem_u32(Bs[1]);

    float acc[4][4][4];
#pragma unroll
    for (int i = 0; i < 4; i++)
#pragma unroll
        for (int j = 0; j < 4; j++)
#pragma unroll
            for (int e = 0; e < 4; e++) acc[i][j][e] = 0.f;

    const int ldrow = tid >> 2;
    const int ldkc  = tid & 3;

    {
#pragma unroll
        for (int l = 0; l < 2; ++l) {
            int row = ldrow + l * 64;
            uint32_t off = swz(row, ldkc);
            cp_async16(sA0 + off, A3 + (size_t)(m0 + row) * K3_ + ldkc * 8);
            cp_async16(sB0 + off, B3 + (size_t)(n0 + row) * K3_ + ldkc * 8);
        }
        CP_COMMIT();
    }

    const int lmat = lane >> 3, lr = lane & 7;

    for (int c = 0; c < NIT; ++c) {
        const int buf = c & 1;
        const uint32_t sa = buf ? sA1 : sA0;
        const uint32_t sb = buf ? sB1 : sB0;

        if (c + 1 < NIT) {
            const uint32_t na = buf ? sA0 : sA1;
            const uint32_t nb = buf ? sB0 : sB1;
            const int k0 = (c + 1) * 32;
#pragma unroll
            for (int l = 0; l < 2; ++l) {
                int row = ldrow + l * 64;
                uint32_t off = swz(row, ldkc);
                cp_async16(na + off, A3 + (size_t)(m0 + row) * K3_ + k0 + ldkc * 8);
                cp_async16(nb + off, B3 + (size_t)(n0 + row) * K3_ + k0 + ldkc * 8);
            }
            CP_COMMIT();
            asm volatile("cp.async.wait_group 1;");
        } else {
            asm volatile("cp.async.wait_group 0;");
        }
        __syncthreads();

#pragma unroll
        for (int s = 0; s < 2; ++s) {
            uint32_t a[4][4], b[4][2];
#pragma unroll
            for (int i = 0; i < 4; ++i) {
                int row = wm + i * 16 + (lmat & 1) * 8 + lr;
                int kc  = s * 2 + (lmat >> 1);
                ldsm4(a[i][0], a[i][1], a[i][2], a[i][3], sa + swz(row, kc));
            }
#pragma unroll
            for (int j = 0; j < 2; ++j) {
                int row = wn + j * 16 + (lmat >> 1) * 8 + lr;
                int kc  = s * 2 + (lmat & 1);
                uint32_t t0, t1, t2, t3;
                ldsm4(t0, t1, t2, t3, sb + swz(row, kc));
                b[j * 2][0] = t0;     b[j * 2][1] = t1;
                b[j * 2 + 1][0] = t2; b[j * 2 + 1][1] = t3;
            }
#pragma unroll
            for (int i = 0; i < 4; ++i)
#pragma unroll
                for (int j = 0; j < 4; ++j)
                    mma16816(acc[i][j], a[i], b[j]);
        }
        __syncthreads();
    }

    const int er = lane >> 2, ec = (lane & 3) * 2;
#pragma unroll
    for (int i = 0; i < 4; ++i) {
#pragma unroll
        for (int j = 0; j < 4; ++j) {
            size_t row = (size_t)(m0 + wm + i * 16 + er);
            int col = n0 + wn + j * 8 + ec;
            *(float2*)&C[row * N + col]       = make_float2(acc[i][j][0], acc[i][j][1]);
            *(float2*)&C[(row + 8) * N + col] = make_float2(acc[i][j][2], acc[i][j][3]);
        }
    }
}

// ---------------------------------------------------------------------------
// RoPE + head split -> bf16 hi/lo panels; V written TRANSPOSED [bh][d][S].
// ---------------------------------------------------------------------------
__global__ void rope_split_bf(const float* __restrict__ qkv)
{
    int idx = blockIdx.x * blockDim.x + threadIdx.x;
    const int total = B_ * S_ * H_ * (HD_ / 2);
    if (idx >= total) return;

    int i = idx & 31;
    int t = idx >> 5;
    int h = t & (H_ - 1);
    t >>= 4;
    int s = t & (S_ - 1);
    int b = t >> 11;
    int bh = b * H_ + h;

    const float* row = qkv + (size_t)(b * S_ + s) * N_QKV;
    int col = h * HD_ + 2 * i;

    float q0 = row[col],          q1 = row[col + 1];
    float k0 = row[D_ + col],     k1 = row[D_ + col + 1];
    float v0 = row[2 * D_ + col], v1 = row[2 * D_ + col + 1];

    float inv_freq = (float)pow(10000.0, -(double)(2 * i) / (double)HD_);
    float ang = (float)s * inv_freq;
    float c = cosf(ang), sn = sinf(ang);

    float qr0 = q0 * c - q1 * sn, qr1 = q0 * sn + q1 * c;
    float kr0 = k0 * c - k1 * sn, kr1 = k0 * sn + k1 * c;

    size_t off = ((size_t)bh * S_ + s) * HD_ + 2 * i;
    __nv_bfloat16 hq0 = __float2bfloat16(qr0), hq1 = __float2bfloat16(qr1);
    __nv_bfloat16 hk0 = __float2bfloat16(kr0), hk1 = __float2bfloat16(kr1);
    g_qhi[off]     = hq0; g_qhi[off + 1] = hq1;
    g_qlo[off]     = __float2bfloat16(qr0 - __bfloat162float(hq0));
    g_qlo[off + 1] = __float2bfloat16(qr1 - __bfloat162float(hq1));
    g_khi[off]     = hk0; g_khi[off + 1] = hk1;
    g_klo[off]     = __float2bfloat16(kr0 - __bfloat162float(hk0));
    g_klo[off + 1] = __float2bfloat16(kr1 - __bfloat162float(hk1));

    size_t tv0 = ((size_t)bh * HD_ + 2 * i) * S_ + s;
    size_t tv1 = ((size_t)bh * HD_ + 2 * i + 1) * S_ + s;
    __nv_bfloat16 hv0 = __float2bfloat16(v0), hv1 = __float2bfloat16(v1);
    g_vthi[tv0] = hv0;
    g_vthi[tv1] = hv1;
    g_vtlo[tv0] = __float2bfloat16(v0 - __bfloat162float(hv0));
    g_vtlo[tv1] = __float2bfloat16(v1 - __bfloat162float(hv1));
}

// ---------------------------------------------------------------------------
// HMMA flash attention v3: 256 threads / 8 warps, 16 query rows per warp.
// 4 warps/SMSP at 2 CTAs/SM -> softmax latency hidden behind peer MMAs.
// MUFU ex2 softmax, double-buffered K/V, mask by -3e38 (ex2 underflow).
// ---------------------------------------------------------------------------
#define K2E 0.18033688011112042f   // 0.125 * log2(e)
#define MASKV -3.0e38f

__global__ __launch_bounds__(256, 2) void flash_hmma(const int* __restrict__ pad,
                                                     __nv_bfloat16* __restrict__ O3)
{
    extern __shared__ __align__(128) char fsm[];
    const uint32_t sQ  = smem_u32(fsm);          // [128][256B] 32KB
    const uint32_t sK0 = sQ + 32768;             // [64][256B]  16KB
    const uint32_t sV0 = sQ + 49152;
    const uint32_t sK1 = sQ + 65536;
    const uint32_t sV1 = sQ + 81920;
    __shared__ float maddS[2][64];

    const int bh = blockIdx.y;
    const int b = bh >> 4;
    const int hh = bh & 15;
    const int qt = blockIdx.x;
    const int q0 = qt * 128;
    const int tid = threadIdx.x;
    const int wid = tid >> 5, lane = tid & 31;
    const int wm = wid * 16;                     // 16 rows per warp
    const int lmat = lane >> 3, lr = lane & 7;

    const __nv_bfloat16* qh = g_qhi + (size_t)bh * S_ * HD_;
    const __nv_bfloat16* ql = g_qlo + (size_t)bh * S_ * HD_;
    const __nv_bfloat16* kh = g_khi + (size_t)bh * S_ * HD_;
    const __nv_bfloat16* kl = g_klo + (size_t)bh * S_ * HD_;
    const __nv_bfloat16* vh = g_vthi + (size_t)bh * HD_ * S_;
    const __nv_bfloat16* vl = g_vtlo + (size_t)bh * HD_ * S_;

    // ---- prologue: Q tile (group), then K/V tile 0 (group)
#pragma unroll
    for (int l = 0; l < 8; ++l) {
        int slot = l * 256 + tid;        // 0..2047
        int row = slot >> 4, c = slot & 15;
        const __nv_bfloat16* src = (c < 8)
            ? qh + (size_t)(q0 + row) * HD_ + c * 8
            : ql + (size_t)(q0 + row) * HD_ + (c - 8) * 8;
        cp_async16(sQ + swz16(row, c), src);
    }
    CP_COMMIT();
#pragma unroll
    for (int l = 0; l < 4; ++l) {
        int slot = l * 256 + tid;        // 0..1023
        int row = slot >> 4, c = slot & 15;
        const __nv_bfloat16* srck = (c < 8)
            ? kh + (size_t)row * HD_ + c * 8
            : kl + (size_t)row * HD_ + (c - 8) * 8;
        cp_async16(sK0 + swz16(row, c), srck);
        const __nv_bfloat16* srcv = (c < 8)
            ? vh + (size_t)row * S_ + c * 8
            : vl + (size_t)row * S_ + (c - 8) * 8;
        cp_async16(sV0 + swz16(row, c), srcv);
    }
    CP_COMMIT();
    if (tid < 64)
        maddS[0][tid] = pad[b * S_ + tid] ? 0.f : MASKV;

    float m_[2], l_[2], oacc[8][4];
#pragma unroll
    for (int h2 = 0; h2 < 2; h2++) { m_[h2] = -1e30f; l_[h2] = 0.f; }
#pragma unroll
    for (int n = 0; n < 8; n++)
#pragma unroll
        for (int e = 0; e < 4; e++) oacc[n][e] = 0.f;

    const int nTiles = qt * 2 + 2;

    for (int kt = 0; kt < nTiles; ++kt) {
        const int buf = kt & 1;
        const uint32_t sK = buf ? sK1 : sK0;
        const uint32_t sV = buf ? sV1 : sV0;

        // prefetch tile kt+1 into the other buffer
        if (kt + 1 < nTiles) {
            const uint32_t nK = buf ? sK0 : sK1;
            const uint32_t nV = buf ? sV0 : sV1;
            const int nv0 = (kt + 1) * 64;
#pragma unroll
            for (int l = 0; l < 4; ++l) {
                int slot = l * 256 + tid;
                int row = slot >> 4, c = slot & 15;
                const __nv_bfloat16* srck = (c < 8)
                    ? kh + (size_t)(nv0 + row) * HD_ + c * 8
                    : kl + (size_t)(nv0 + row) * HD_ + (c - 8) * 8;
                cp_async16(nK + swz16(row, c), srck);
                const __nv_bfloat16* srcv = (c < 8)
                    ? vh + (size_t)row * S_ + nv0 + c * 8
                    : vl + (size_t)row * S_ + nv0 + (c - 8) * 8;
                cp_async16(nV + swz16(row, c), srcv);
            }
            CP_COMMIT();
            if (tid < 64)
                maddS[(kt + 1) & 1][tid] = pad[b * S_ + nv0 + tid] ? 0.f : MASKV;
            asm volatile("cp.async.wait_group 1;");
        } else {
            asm volatile("cp.async.wait_group 0;");
        }
        __syncthreads();

        const int kv0 = kt * 64;
        if (kv0 <= q0 + wm + 15) {     // warp-level causal skip (16-row grain)
            // ---- S = Q K^T, 3-term split (12 k16 steps)
            float sacc[8][4];
#pragma unroll
            for (int n = 0; n < 8; n++)
#pragma unroll
                for (int e = 0; e < 4; e++) sacc[n][e] = 0.f;

#pragma unroll
            for (int st = 0; st < 12; ++st) {
                int akc = (st < 4) ? st * 2 : (st < 8) ? 8 + (st - 4) * 2 : (st - 8) * 2;
                int bkc = (st < 8) ? (st & 3) * 2 : 8 + (st - 8) * 2;
                uint32_t a[4], bb[8][2];
                {
                    int row = wm + (lmat & 1) * 8 + lr;
                    ldsm4(a[0], a[1], a[2], a[3],
                          sQ + swz16(row, akc + (lmat >> 1)));
                }
#pragma unroll
                for (int j = 0; j < 4; ++j) {
                    int row = j * 16 + (lmat >> 1) * 8 + lr;
                    uint32_t t0, t1, t2, t3;
                    ldsm4(t0, t1, t2, t3, sK + swz16(row, bkc + (lmat & 1)));
                    bb[j * 2][0] = t0;     bb[j * 2][1] = t1;
                    bb[j * 2 + 1][0] = t2; bb[j * 2 + 1][1] = t3;
                }
#pragma unroll
                for (int n = 0; n < 8; ++n)
                    mma16816(sacc[n], a, bb[n]);
            }

            // ---- mask + scale into base-2 domain
            const bool doCausal = (kv0 + 63 > q0 + wm);
#pragma unroll
            for (int n = 0; n < 8; ++n) {
                float md0 = maddS[buf][n * 8 + (lane & 3) * 2];
                float md1 = maddS[buf][n * 8 + (lane & 3) * 2 + 1];
#pragma unroll
                for (int e = 0; e < 4; ++e) {
                    float x = fmaf(sacc[n][e], K2E, (e & 1) ? md1 : md0);
                    if (doCausal) {
                        int key = kv0 + n * 8 + (lane & 3) * 2 + (e & 1);
                        int rw  = q0 + wm + (lane >> 2) + (e >> 1) * 8;
                        if (key > rw) x = MASKV;
                    }
                    sacc[n][e] = x;
                }
            }

            // ---- online softmax (MUFU ex2)
#pragma unroll
            for (int h2 = 0; h2 < 2; ++h2) {
                float mx = MASKV;
#pragma unroll
                for (int n = 0; n < 8; ++n)
                    mx = fmaxf(mx, fmaxf(sacc[n][h2 * 2], sacc[n][h2 * 2 + 1]));
                mx = fmaxf(mx, __shfl_xor_sync(0xffffffffu, mx, 1));
                mx = fmaxf(mx, __shfl_xor_sync(0xffffffffu, mx, 2));
                float mnew = fmaxf(m_[h2], mx);
                float alpha = ex2(m_[h2] - mnew);
                float rs = 0.f;
#pragma unroll
                for (int n = 0; n < 8; ++n) {
#pragma unroll
                    for (int e = h2 * 2; e < h2 * 2 + 2; ++e) {
                        float p = ex2(sacc[n][e] - mnew);
                        sacc[n][e] = p;
                        rs += p;
                    }
                }
                rs += __shfl_xor_sync(0xffffffffu, rs, 1);
                rs += __shfl_xor_sync(0xffffffffu, rs, 2);
                l_[h2] = l_[h2] * alpha + rs;
                m_[h2] = mnew;
#pragma unroll
                for (int n = 0; n < 8; ++n) {
                    oacc[n][h2 * 2]     *= alpha;
                    oacc[n][h2 * 2 + 1] *= alpha;
                }
            }

            // ---- O += P V (3-term); pack P per kk, V-frags per nd-pair
#pragma unroll
            for (int kk = 0; kk < 4; ++kk) {
                uint32_t aphi[4], aplo[4];
#pragma unroll
                for (int half = 0; half < 2; ++half) {
                    int n = 2 * kk + half;
#pragma unroll
                    for (int pr = 0; pr < 2; ++pr) {
                        float p0 = sacc[n][pr * 2];
                        float p1 = sacc[n][pr * 2 + 1];
                        uint32_t hi = pack_bf2(p0, p1);
                        __nv_bfloat162 h2v = *reinterpret_cast<__nv_bfloat162*>(&hi);
                        aphi[half * 2 + pr] = hi;
                        aplo[half * 2 + pr] =
                            pack_bf2(p0 - __bfloat162float(h2v.x),
                                     p1 - __bfloat162float(h2v.y));
                    }
                }
#pragma unroll
                for (int g = 0; g < 4; ++g) {
                    int row = g * 16 + (lmat >> 1) * 8 + lr;
                    uint32_t t0, t1, t2, t3, u0, u1, u2, u3;
                    ldsm4(t0, t1, t2, t3, sV + swz16(row, kk * 2 + (lmat & 1)));
                    ldsm4(u0, u1, u2, u3, sV + swz16(row, 8 + kk * 2 + (lmat & 1)));
                    uint32_t bh0[2] = {t0, t1}, bh1[2] = {t2, t3};
                    uint32_t bl0[2] = {u0, u1}, bl1[2] = {u2, u3};
                    mma16816(oacc[2 * g],     aphi, bh0);
                    mma16816(oacc[2 * g],     aplo, bh0);
                    mma16816(oacc[2 * g],     aphi, bl0);
                    mma16816(oacc[2 * g + 1], aphi, bh1);
                    mma16816(oacc[2 * g + 1], aplo, bh1);
                    mma16816(oacc[2 * g + 1], aphi, bl1);
                }
            }
        }
        __syncthreads();
    }

    // ---- epilogue: normalize, write bf16x3 [hi|lo|hi]
#pragma unroll
    for (int h2 = 0; h2 < 2; ++h2) {
        float inv = (l_[h2] > 0.f) ? (1.f / l_[h2]) : 0.f;
        int srow = q0 + wm + (lane >> 2) + h2 * 8;
        size_t token = (size_t)b * S_ + srow;
#pragma unroll
        for (int nd = 0; nd < 8; ++nd) {
            float v0 = oacc[nd][h2 * 2] * inv;
            float v1 = oacc[nd][h2 * 2 + 1] * inv;
            __nv_bfloat162 hi2 = __floats2bfloat162_rn(v0, v1);
            __nv_bfloat162 lo2 = __floats2bfloat162_rn(
                v0 - __bfloat162float(hi2.x), v1 - __bfloat162float(hi2.y));
            size_t base = token * K3_ + hh * HD_ + nd * 8 + (lane & 3) * 2;
            *(__nv_bfloat162*)(O3 + base)        = hi2;
            *(__nv_bfloat162*)(O3 + base + 1024) = lo2;
            *(__nv_bfloat162*)(O3 + base + 2048) = hi2;
        }
    }
}

// ---------------------------------------------------------------------------
// Launch
// ---------------------------------------------------------------------------
#define FLASH_SMEM 98304   // Q 32KB + 2 x (K 16KB + V 16KB)

extern "C" void kernel_launch(void* const* d_in, const int* in_sizes, int n_in,
                              void* d_out, int out_size)
{
    const float* x     = (const float*)d_in[0];
    const int*   pad   = (const int*)d_in[1];
    const float* w_qkv = (const float*)d_in[2];
    const float* w_o   = (const float*)d_in[3];
    float* out = (float*)d_out;

    float* qkv;
    __nv_bfloat16 *x3, *wqkv3, *wo3, *attn3;
    cudaGetSymbolAddress((void**)&qkv,   g_qkv);
    cudaGetSymbolAddress((void**)&x3,    g_x3);
    cudaGetSymbolAddress((void**)&wqkv3, g_wqkv3);
    cudaGetSymbolAddress((void**)&wo3,   g_wo3);
    cudaGetSymbolAddress((void**)&attn3, g_attn3);

    cudaFuncSetAttribute(flash_hmma, cudaFuncAttributeMaxDynamicSharedMemorySize,
                         FLASH_SMEM);

    // 0) fp32 -> bf16x3 splits
    {
        int txc = M_ * D_;
        conv_bf16x3<<<(txc + 255) / 256, 256>>>(x, x3, txc, 1);
        int tw = N_QKV * D_;
        conv_bf16x3<<<(tw + 255) / 256, 256>>>(w_qkv, wqkv3, tw, 0);
        int to = D_ * D_;
        conv_bf16x3<<<(to + 255) / 256, 256>>>(w_o, wo3, to, 0);
    }

    // 1) QKV projection (HMMA)
    {
        dim3 grid(N_QKV / 128, M_ / 128);
        gemm_hmma<<<grid, 256>>>(x3, wqkv3, qkv, N_QKV);
    }

    // 2) RoPE + head split into bf16 hi/lo panels (V transposed)
    {
        int total = B_ * S_ * H_ * (HD_ / 2);
        rope_split_bf<<<(total + 255) / 256, 256>>>(qkv);
    }

    // 3) HMMA flash attention v3 (8 warps)
    {
        dim3 grid(S_ / 128, B_ * H_);
        flash_hmma<<<grid, 256, FLASH_SMEM>>>(pad, attn3);
    }

    // 4) Output projection (HMMA) -> d_out (fp32)
    {
        dim3 grid(D_ / 128, M_ / 128);
        gemm_hmma<<<grid, 256>>>(attn3, wo3, out, D_);
    }
}